// round 12
// baseline (speedup 1.0000x reference)
#include <cuda_runtime.h>
#include <cuda_bf16.h>
#include <math.h>
#include <stdint.h>

#define NN    50000
#define NFEAT 256
#define NH    128
#define NC    64
#define NE    800000

// ---------------- static scratch ----------------
__device__ __align__(16) __nv_bfloat16 g_xorg[(size_t)NN*NH];
__device__ __align__(16) __nv_bfloat16 g_tb  [(size_t)NN*NH];
__device__ __align__(16) __nv_bfloat16 g_x1  [(size_t)NN*NH];
__device__ __align__(16) __nv_bfloat16 g_x2  [(size_t)NN*NH];
__device__ __align__(16) __nv_bfloat16 g_t3  [(size_t)NN*NC];
__device__ __align__(16) __nv_bfloat16 g_wenc [NH*NFEAT];   // [N=128][K=256]
__device__ __align__(16) __nv_bfloat16 g_wgc1 [NH*NH];
__device__ __align__(16) __nv_bfloat16 g_wgc2 [NH*NH];
__device__ __align__(16) __nv_bfloat16 g_wgc3 [NC*NH];      // [64][128]
__device__ __align__(16) __nv_bfloat16 g_wnode[5*NH*NH];    // permuted [640][128]
__device__ __align__(16) __nv_bfloat16 g_wnei [5*NH*NH];
__device__ float g_bnp [5*NH];
__device__ float g_bvp1[5*NH];   // b_nei' + b_gc1 @ W_nei  (permuted)
__device__ float g_bvp2[5*NH];   // b_nei' + b_gc2 @ W_nei  (permuted)
__device__ int   g_cnt[NN+1];
__device__ int   g_rowptr[NN+1];
__device__ int   g_fill[NN];
__device__ int   g_sdst[NE];
__device__ float g_sval[NE];

// ---------------- PTX helpers (sm_80+ portable; no tcgen05) ----------------
__device__ __forceinline__ uint32_t smem_u32(const void* p){
    uint32_t a;
    asm("{ .reg .u64 t; cvta.to.shared.u64 t, %1; cvt.u32.u64 %0, t; }" : "=r"(a) : "l"(p));
    return a;
}
__device__ __forceinline__ void ldsm_x4(uint32_t* r, uint32_t addr){
    asm volatile("ldmatrix.sync.aligned.m8n8.x4.shared.b16 {%0,%1,%2,%3}, [%4];"
        : "=r"(r[0]),"=r"(r[1]),"=r"(r[2]),"=r"(r[3]) : "r"(addr));
}
__device__ __forceinline__ void ldsm_x2(uint32_t* r, uint32_t addr){
    asm volatile("ldmatrix.sync.aligned.m8n8.x2.shared.b16 {%0,%1}, [%2];"
        : "=r"(r[0]),"=r"(r[1]) : "r"(addr));
}
__device__ __forceinline__ void mma16816(float* c, const uint32_t* a, const uint32_t* b){
    asm volatile("mma.sync.aligned.m16n8k16.row.col.f32.bf16.bf16.f32 "
        "{%0,%1,%2,%3}, {%4,%5,%6,%7}, {%8,%9}, {%0,%1,%2,%3};"
        : "+f"(c[0]), "+f"(c[1]), "+f"(c[2]), "+f"(c[3])
        : "r"(a[0]), "r"(a[1]), "r"(a[2]), "r"(a[3]), "r"(b[0]), "r"(b[1]));
}
__device__ __forceinline__ float warp_sum(float v){
    #pragma unroll
    for(int o=16;o;o>>=1) v += __shfl_xor_sync(0xffffffffu, v, o);
    return v;
}
__device__ __forceinline__ float warp_max(float v){
    #pragma unroll
    for(int o=16;o;o>>=1) v = fmaxf(v, __shfl_xor_sync(0xffffffffu, v, o));
    return v;
}
__device__ __forceinline__ float bf2f(__nv_bfloat16 b){ return __bfloat162float(b); }

// ---------------- CSR build ----------------
__global__ void count_kernel(const int* __restrict__ src, int* cnt, int ne){
    int i = blockIdx.x*blockDim.x + threadIdx.x;
    if(i < ne) atomicAdd(&cnt[src[i]], 1);
}
__global__ void scan_kernel(const int* __restrict__ cnt, int* rowptr, int* fill, int n){
    __shared__ int sh[1024];
    int tid = threadIdx.x;
    int chunk = (n + 1023) >> 10;
    int s0 = tid*chunk, s1 = min(s0+chunk, n);
    int s = 0;
    for(int i=s0;i<s1;i++) s += cnt[i];
    sh[tid] = s;
    __syncthreads();
    for(int off=1; off<1024; off<<=1){
        int v = (tid >= off) ? sh[tid-off] : 0;
        __syncthreads();
        sh[tid] += v;
        __syncthreads();
    }
    int run = sh[tid] - s;
    for(int i=s0;i<s1;i++){
        rowptr[i] = run; fill[i] = run; run += cnt[i];
    }
    if(tid == 1023) rowptr[n] = sh[1023];
}
__global__ void scatter_kernel(const int* __restrict__ src, const int* __restrict__ dst,
                               const float* __restrict__ val,
                               int* fill, int* sdst, float* sval, int ne){
    int i = blockIdx.x*blockDim.x + threadIdx.x;
    if(i < ne){
        int p = atomicAdd(&fill[src[i]], 1);
        sdst[p] = dst[i];
        sval[p] = val[i];
    }
}

// ---------------- fused weight prep (+ cnt zero, + bias folding) ----------------
__global__ void prep_all(const float* __restrict__ W_enc, const float* __restrict__ W_gc1,
                         const float* __restrict__ W_gc2, const float* __restrict__ W_gc3,
                         const float* __restrict__ Wn,    const float* __restrict__ Wv,
                         const float* __restrict__ bn,    const float* __restrict__ bv,
                         const float* __restrict__ bgc1,  const float* __restrict__ bgc2,
                         __nv_bfloat16* wenc, __nv_bfloat16* wgc1, __nv_bfloat16* wgc2,
                         __nv_bfloat16* wgc3, __nv_bfloat16* wn_t, __nv_bfloat16* wv_t,
                         float* bn_p, float* bv_p1, float* bv_p2, int* cnt)
{
    int i = blockIdx.x*256 + threadIdx.x;
    if(i < NN + 1) cnt[i] = 0;
    if(i < NH*NFEAT){
        int n = i / NFEAT, k = i % NFEAT;
        wenc[i] = __float2bfloat16(W_enc[(size_t)k*NH + n]);
    }
    if(i < NH*NH){
        int n = i / NH, k = i % NH;
        wgc1[i] = __float2bfloat16(W_gc1[(size_t)k*NH + n]);
        wgc2[i] = __float2bfloat16(W_gc2[(size_t)k*NH + n]);
    }
    if(i < NC*NH){
        int n = i / NH, k = i % NH;
        wgc3[i] = __float2bfloat16(W_gc3[(size_t)k*NC + n]);
    }
    if(i < 640*128){
        int np = i >> 7, k = i & 127;
        int t = np >> 7, j = np & 127;
        int col = j*5 + t;
        wn_t[i] = __float2bfloat16(Wn[(size_t)k*640 + col]);
        wv_t[i] = __float2bfloat16(Wv[(size_t)k*640 + col]);
    }
    if(i < 640){
        int t = i >> 7, j = i & 127;
        int col = j*5 + t;
        bn_p[i] = bn[col];
        // fold gc bias through W_nei:  bv' = bv + b_gc @ W_nei[:, col]
        float d1 = 0.f, d2 = 0.f;
        for(int k = 0; k < NH; k++){
            float w = Wv[(size_t)k*640 + col];
            d1 += bgc1[k] * w;
            d2 += bgc2[k] * w;
        }
        bv_p1[i] = bv[col] + d1;
        bv_p2[i] = bv[col] + d2;
    }
}

// ---------------- bf16 warp-MMA GEMM ----------------
// C[M][BN] = A[M][K] @ Bt[BN][K]^T (+bias). A fp32 or bf16; C fp32 or bf16.
// 256 threads = 8 warps as 4(M) x 2(N). Block tile 128 x BN.
template<int BN, int K, bool BIAS, bool INBF, bool OUTBF>
__global__ __launch_bounds__(256) void mma_gemm(
    const void* __restrict__ Ain, const __nv_bfloat16* __restrict__ Bt,
    const float* __restrict__ bias, void* __restrict__ Cout, int M)
{
    constexpr int P  = K + 8;
    constexpr int NW = BN / 2;
    constexpr int NF = NW / 8;
    extern __shared__ __align__(16) char smem[];
    __nv_bfloat16* As = (__nv_bfloat16*)smem;
    __nv_bfloat16* Bs = As + 128*P;
    float* bias_s = (float*)(Bs + (size_t)BN*P);

    const int tid = threadIdx.x, lane = tid & 31, wid = tid >> 5;
    const int wm = wid & 3, wn = wid >> 2;
    const int bm = blockIdx.x * 128;

    if(INBF){
        const __nv_bfloat16* A = (const __nv_bfloat16*)Ain;
        for(int i=tid; i<128*(K/8); i+=256){
            int r = i / (K/8), k = (i % (K/8)) * 8;
            uint4 u = make_uint4(0u,0u,0u,0u);
            if(bm + r < M) u = *(const uint4*)(A + (size_t)(bm+r)*K + k);
            *(uint4*)&As[r*P + k] = u;
        }
    } else {
        const float* A = (const float*)Ain;
        for(int i=tid; i<128*(K/4); i+=256){
            int r = i / (K/4), k = (i % (K/4)) * 4;
            float4 v = make_float4(0.f,0.f,0.f,0.f);
            if(bm + r < M) v = *(const float4*)(A + (size_t)(bm+r)*K + k);
            __nv_bfloat162 lo = __floats2bfloat162_rn(v.x, v.y);
            __nv_bfloat162 hi = __floats2bfloat162_rn(v.z, v.w);
            uint2 u; u.x = *(uint32_t*)&lo; u.y = *(uint32_t*)&hi;
            *(uint2*)&As[r*P + k] = u;
        }
    }
    for(int i=tid; i<BN*(K/8); i+=256){
        int r = i / (K/8), k = (i % (K/8)) * 8;
        *(uint4*)&Bs[r*P + k] = *(const uint4*)(Bt + (size_t)r*K + k);
    }
    if(BIAS){ for(int i=tid; i<BN; i+=256) bias_s[i] = bias[i]; }
    __syncthreads();

    const uint32_t as_b = smem_u32(As);
    const uint32_t bs_b = smem_u32(Bs);

    float acc[2][NF][4];
    #pragma unroll
    for(int f=0;f<2;f++)
        #pragma unroll
        for(int g=0;g<NF;g++)
            #pragma unroll
            for(int v=0;v<4;v++) acc[f][g][v] = 0.f;

    #pragma unroll
    for(int k0=0; k0<K; k0+=16){
        uint32_t a[2][4];
        #pragma unroll
        for(int f=0;f<2;f++)
            ldsm_x4(a[f], as_b + (uint32_t)(((wm*32 + f*16 + (lane&15))*P + k0 + (lane>>4)*8) << 1));
        uint32_t b[NF][2];
        #pragma unroll
        for(int g=0;g<NF;g++)
            ldsm_x2(b[g], bs_b + (uint32_t)(((wn*NW + g*8 + (lane&7))*P + k0 + ((lane>>3)&1)*8) << 1));
        #pragma unroll
        for(int f=0;f<2;f++)
            #pragma unroll
            for(int g=0;g<NF;g++)
                mma16816(acc[f][g], a[f], b[g]);
    }

    #pragma unroll
    for(int f=0;f<2;f++){
        int r0 = bm + wm*32 + f*16 + (lane>>2);
        #pragma unroll
        for(int g=0;g<NF;g++){
            int c = wn*NW + g*8 + (lane&3)*2;
            float bx = BIAS ? bias_s[c]   : 0.f;
            float by = BIAS ? bias_s[c+1] : 0.f;
            if(OUTBF){
                __nv_bfloat16* C = (__nv_bfloat16*)Cout;
                if(r0 < M)
                    *(__nv_bfloat162*)(C + (size_t)r0*BN + c) =
                        __floats2bfloat162_rn(acc[f][g][0]+bx, acc[f][g][1]+by);
                if(r0 + 8 < M)
                    *(__nv_bfloat162*)(C + (size_t)(r0+8)*BN + c) =
                        __floats2bfloat162_rn(acc[f][g][2]+bx, acc[f][g][3]+by);
            } else {
                float* C = (float*)Cout;
                if(r0 < M)
                    *(float2*)(C + (size_t)r0*BN + c) = make_float2(acc[f][g][0]+bx, acc[f][g][1]+by);
                if(r0 + 8 < M)
                    *(float2*)(C + (size_t)(r0+8)*BN + c) = make_float2(acc[f][g][2]+bx, acc[f][g][3]+by);
            }
        }
    }
}

// ---------------- fused spmm + bilinear pool (64-row blocks, 2 CTAs/SM) ----------------
// Phase 1: A2 = spmm(TB) for this block's 64 rows (CSR gather, fp32 acc -> bf16 smem).
// Phase 2: for t in 0..4: U = A1@Wn_t^T, V = A2@Wv_t^T; acc += (U+bn)*(V+bv').
// bv' is pre-adjusted with the folded gc bias. Then signed sqrt + row L2 norm.
__global__ __launch_bounds__(256,2) void mma_pool(
    const __nv_bfloat16* __restrict__ A1, const __nv_bfloat16* __restrict__ TB,
    const int* __restrict__ rowptr, const int* __restrict__ sdst,
    const float* __restrict__ sval,
    const __nv_bfloat16* __restrict__ Wn, const __nv_bfloat16* __restrict__ Wv,
    const float* __restrict__ bnp, const float* __restrict__ bvp,
    __nv_bfloat16* __restrict__ Out, int M)
{
    constexpr int K = 128, P = K + 8;
    extern __shared__ __align__(16) char smem[];
    __nv_bfloat16* A1s = (__nv_bfloat16*)smem;       // 64 x P
    __nv_bfloat16* A2s = A1s + 64*P;
    __nv_bfloat16* Bns = A2s + 64*P;                 // 128 x P
    __nv_bfloat16* Bvs = Bns + 128*P;
    float* bn_s   = (float*)(Bvs + 128*P);           // 640
    float* bv_s   = bn_s + 640;
    float* rowsum = bv_s + 640;                      // 64

    const int tid = threadIdx.x, lane = tid & 31, wid = tid >> 5;
    const int wm = wid & 1, wn = wid >> 1;           // 2 x 4
    const int bm = blockIdx.x * 64;

    // A1 tile (bf16 straight copy)
    for(int i=tid; i<64*16; i+=256){
        int r = i >> 4, k = (i & 15) * 8;
        uint4 u1 = make_uint4(0u,0u,0u,0u);
        if(bm + r < M) u1 = *(const uint4*)(A1 + (size_t)(bm+r)*K + k);
        *(uint4*)&A1s[r*P + k] = u1;
    }
    for(int i=tid; i<640; i+=256){ bn_s[i] = bnp[i]; bv_s[i] = bvp[i]; }
    if(tid < 64) rowsum[tid] = 0.f;

    // ---- phase 1: spmm for this block's 64 rows (warp-per-row, 8 rows/warp) ----
    for(int rr=0; rr<8; rr++){
        int lr = wid*8 + rr;       // 0..63
        int grow = bm + lr;
        float4 a0 = make_float4(0.f,0.f,0.f,0.f);
        float4 a1 = a0, a2 = a0, a3 = a0;
        if(grow < M){
            int b = rowptr[grow], e = rowptr[grow+1];
            int j = b;
            for(; j+3 < e; j+=4){
                int d0 = sdst[j], d1 = sdst[j+1], d2 = sdst[j+2], d3 = sdst[j+3];
                float v0 = sval[j], v1 = sval[j+1], v2 = sval[j+2], v3 = sval[j+3];
                uint2 u0 = *(const uint2*)(TB + (size_t)d0*NH + lane*4);
                uint2 u1 = *(const uint2*)(TB + (size_t)d1*NH + lane*4);
                uint2 u2 = *(const uint2*)(TB + (size_t)d2*NH + lane*4);
                uint2 u3 = *(const uint2*)(TB + (size_t)d3*NH + lane*4);
                __nv_bfloat162 p0 = *(__nv_bfloat162*)&u0.x, q0 = *(__nv_bfloat162*)&u0.y;
                __nv_bfloat162 p1 = *(__nv_bfloat162*)&u1.x, q1 = *(__nv_bfloat162*)&u1.y;
                __nv_bfloat162 p2 = *(__nv_bfloat162*)&u2.x, q2 = *(__nv_bfloat162*)&u2.y;
                __nv_bfloat162 p3 = *(__nv_bfloat162*)&u3.x, q3 = *(__nv_bfloat162*)&u3.y;
                a0.x += v0*bf2f(p0.x); a0.y += v0*bf2f(p0.y); a0.z += v0*bf2f(q0.x); a0.w += v0*bf2f(q0.y);
                a1.x += v1*bf2f(p1.x); a1.y += v1*bf2f(p1.y); a1.z += v1*bf2f(q1.x); a1.w += v1*bf2f(q1.y);
                a2.x += v2*bf2f(p2.x); a2.y += v2*bf2f(p2.y); a2.z += v2*bf2f(q2.x); a2.w += v2*bf2f(q2.y);
                a3.x += v3*bf2f(p3.x); a3.y += v3*bf2f(p3.y); a3.z += v3*bf2f(q3.x); a3.w += v3*bf2f(q3.y);
            }
            for(; j < e; j++){
                int d0 = sdst[j]; float v0 = sval[j];
                uint2 u0 = *(const uint2*)(TB + (size_t)d0*NH + lane*4);
                __nv_bfloat162 p0 = *(__nv_bfloat162*)&u0.x, q0 = *(__nv_bfloat162*)&u0.y;
                a0.x += v0*bf2f(p0.x); a0.y += v0*bf2f(p0.y); a0.z += v0*bf2f(q0.x); a0.w += v0*bf2f(q0.y);
            }
        }
        a0.x += a1.x + a2.x + a3.x;
        a0.y += a1.y + a2.y + a3.y;
        a0.z += a1.z + a2.z + a3.z;
        a0.w += a1.w + a2.w + a3.w;
        uint2 o;
        __nv_bfloat162 o0 = __floats2bfloat162_rn(a0.x, a0.y);
        __nv_bfloat162 o1 = __floats2bfloat162_rn(a0.z, a0.w);
        o.x = *(uint32_t*)&o0; o.y = *(uint32_t*)&o1;
        *(uint2*)&A2s[lr*P + lane*4] = o;
    }

    const uint32_t a1_b = smem_u32(A1s);
    const uint32_t a2_b = smem_u32(A2s);
    const uint32_t bn_b = smem_u32(Bns);
    const uint32_t bv_b = smem_u32(Bvs);

    float acc[2][4][4];
    #pragma unroll
    for(int f=0;f<2;f++)
        #pragma unroll
        for(int g=0;g<4;g++)
            #pragma unroll
            for(int v=0;v<4;v++) acc[f][g][v] = 0.f;

    // ---- phase 2: bilinear pool ----
    for(int t=0; t<5; t++){
        __syncthreads();   // t=0: A2s/A1s ready; t>0: prior mma reads done
        for(int i=tid; i<128*16; i+=256){
            int r = i >> 4, k = (i & 15) * 8;
            *(uint4*)&Bns[r*P + k] = *(const uint4*)(Wn + ((size_t)t*128 + r)*K + k);
            *(uint4*)&Bvs[r*P + k] = *(const uint4*)(Wv + ((size_t)t*128 + r)*K + k);
        }
        __syncthreads();

        float U[2][4][4], V[2][4][4];
        #pragma unroll
        for(int f=0;f<2;f++)
            #pragma unroll
            for(int g=0;g<4;g++)
                #pragma unroll
                for(int v=0;v<4;v++){ U[f][g][v]=0.f; V[f][g][v]=0.f; }

        #pragma unroll
        for(int k0=0; k0<K; k0+=16){
            uint32_t a1[2][4], a2[2][4];
            #pragma unroll
            for(int f=0;f<2;f++){
                uint32_t ao = (uint32_t)(((wm*32 + f*16 + (lane&15))*P + k0 + (lane>>4)*8) << 1);
                ldsm_x4(a1[f], a1_b + ao);
                ldsm_x4(a2[f], a2_b + ao);
            }
            uint32_t b1[4][2], b2[4][2];
            #pragma unroll
            for(int g=0;g<4;g++){
                uint32_t bo = (uint32_t)(((wn*32 + g*8 + (lane&7))*P + k0 + ((lane>>3)&1)*8) << 1);
                ldsm_x2(b1[g], bn_b + bo);
                ldsm_x2(b2[g], bv_b + bo);
            }
            #pragma unroll
            for(int f=0;f<2;f++)
                #pragma unroll
                for(int g=0;g<4;g++){
                    mma16816(U[f][g], a1[f], b1[g]);
                    mma16816(V[f][g], a2[f], b2[g]);
                }
        }

        #pragma unroll
        for(int f=0;f<2;f++)
            #pragma unroll
            for(int g=0;g<4;g++){
                int c = wn*32 + g*8 + (lane&3)*2;
                float bnx = bn_s[t*128 + c], bny = bn_s[t*128 + c + 1];
                float bvx = bv_s[t*128 + c], bvy = bv_s[t*128 + c + 1];
                acc[f][g][0] += (U[f][g][0]+bnx)*(V[f][g][0]+bvx);
                acc[f][g][1] += (U[f][g][1]+bny)*(V[f][g][1]+bvy);
                acc[f][g][2] += (U[f][g][2]+bnx)*(V[f][g][2]+bvx);
                acc[f][g][3] += (U[f][g][3]+bny)*(V[f][g][3]+bvy);
            }
    }

    // row |g| sums
    #pragma unroll
    for(int f=0;f<2;f++){
        float s0 = 0.f, s1 = 0.f;
        #pragma unroll
        for(int g=0;g<4;g++){
            s0 += fabsf(acc[f][g][0]) + fabsf(acc[f][g][1]);
            s1 += fabsf(acc[f][g][2]) + fabsf(acc[f][g][3]);
        }
        s0 += __shfl_xor_sync(0xffffffffu, s0, 1);
        s0 += __shfl_xor_sync(0xffffffffu, s0, 2);
        s1 += __shfl_xor_sync(0xffffffffu, s1, 1);
        s1 += __shfl_xor_sync(0xffffffffu, s1, 2);
        if((lane & 3) == 0){
            atomicAdd(&rowsum[wm*32 + f*16 + (lane>>2)], s0);
            atomicAdd(&rowsum[wm*32 + f*16 + (lane>>2) + 8], s1);
        }
    }
    __syncthreads();

    // normalize + store bf16
    #pragma unroll
    for(int f=0;f<2;f++){
        int lr = wm*32 + f*16 + (lane>>2);
        float inv0 = 1.f / fmaxf(sqrtf(rowsum[lr]),     1e-12f);
        float inv1 = 1.f / fmaxf(sqrtf(rowsum[lr + 8]), 1e-12f);
        int r0 = bm + lr;
        #pragma unroll
        for(int g=0;g<4;g++){
            int c = wn*32 + g*8 + (lane&3)*2;
            if(r0 < M){
                float ox = copysignf(sqrtf(fabsf(acc[f][g][0])), acc[f][g][0]) * inv0;
                float oy = copysignf(sqrtf(fabsf(acc[f][g][1])), acc[f][g][1]) * inv0;
                *(__nv_bfloat162*)(Out + (size_t)r0*NH + c) = __floats2bfloat162_rn(ox, oy);
            }
            if(r0 + 8 < M){
                float ox = copysignf(sqrtf(fabsf(acc[f][g][2])), acc[f][g][2]) * inv1;
                float oy = copysignf(sqrtf(fabsf(acc[f][g][3])), acc[f][g][3]) * inv1;
                *(__nv_bfloat162*)(Out + (size_t)(r0+8)*NH + c) = __floats2bfloat162_rn(ox, oy);
            }
        }
    }
}

// ---------------- spmm 64 bf16 cols + bias + log_softmax ----------------
__global__ void spmm64_lsm_kernel(const __nv_bfloat16* __restrict__ t3,
                                  const int* __restrict__ rowptr,
                                  const int* __restrict__ sdst,
                                  const float* __restrict__ sval,
                                  const float* __restrict__ bias,
                                  float* __restrict__ out, int n)
{
    int w = (blockIdx.x*blockDim.x + threadIdx.x) >> 5;
    if(w >= n) return;
    int lane = threadIdx.x & 31;
    int b = rowptr[w], e = rowptr[w+1];

    float2 acc = make_float2(0.f, 0.f);
    float2 acc2 = make_float2(0.f, 0.f);
    int j = b;
    for(; j+1 < e; j+=2){
        int d0 = sdst[j], d1 = sdst[j+1];
        float v0 = sval[j], v1 = sval[j+1];
        __nv_bfloat162 h0 = *(const __nv_bfloat162*)(t3 + (size_t)d0*NC + lane*2);
        __nv_bfloat162 h1 = *(const __nv_bfloat162*)(t3 + (size_t)d1*NC + lane*2);
        acc.x  += v0*bf2f(h0.x); acc.y  += v0*bf2f(h0.y);
        acc2.x += v1*bf2f(h1.x); acc2.y += v1*bf2f(h1.y);
    }
    if(j < e){
        int d = sdst[j]; float v = sval[j];
        __nv_bfloat162 hv = *(const __nv_bfloat162*)(t3 + (size_t)d*NC + lane*2);
        acc.x += v*bf2f(hv.x); acc.y += v*bf2f(hv.y);
    }
    float2 bb = *(const float2*)(bias + lane*2);
    acc.x += acc2.x + bb.x; acc.y += acc2.y + bb.y;

    float m = warp_max(fmaxf(acc.x, acc.y));
    float s = warp_sum(expf(acc.x - m) + expf(acc.y - m));
    float lse = m + logf(s);
    *(float2*)(out + (size_t)w*NC + lane*2) = make_float2(acc.x - lse, acc.y - lse);
}

// ---------------- launch ----------------
#define SYM_ADDR(p, sym) cudaGetSymbolAddress((void**)&(p), sym)

extern "C" void kernel_launch(void* const* d_in, const int* in_sizes, int n_in,
                              void* d_out, int out_size)
{
    const float* x      = (const float*)d_in[0];
    const int*   esrc   = (const int*)  d_in[1];
    const int*   edst   = (const int*)  d_in[2];
    const float* eval   = (const float*)d_in[3];
    const float* W_enc  = (const float*)d_in[4];
    const float* b_enc  = (const float*)d_in[5];
    const float* W_gc1  = (const float*)d_in[6];
    const float* b_gc1  = (const float*)d_in[7];
    const float* W_gc2  = (const float*)d_in[8];
    const float* b_gc2  = (const float*)d_in[9];
    const float* W_gc3  = (const float*)d_in[10];
    const float* b_gc3  = (const float*)d_in[11];
    const float* W_node = (const float*)d_in[12];
    const float* b_node = (const float*)d_in[13];
    const float* W_nei  = (const float*)d_in[14];
    const float* b_nei  = (const float*)d_in[15];
    float* out = (float*)d_out;

    float *sval, *bnp, *bvp1, *bvp2;
    int *cnt, *rowptr, *fill, *sdst;
    __nv_bfloat16 *xorg, *tb, *x1, *x2, *t3;
    __nv_bfloat16 *wenc, *wgc1, *wgc2, *wgc3, *wnode, *wnei;
    SYM_ADDR(xorg, g_xorg);  SYM_ADDR(tb, g_tb);
    SYM_ADDR(x1, g_x1);      SYM_ADDR(x2, g_x2);    SYM_ADDR(t3, g_t3);
    SYM_ADDR(cnt, g_cnt);    SYM_ADDR(rowptr, g_rowptr);
    SYM_ADDR(fill, g_fill);  SYM_ADDR(sdst, g_sdst); SYM_ADDR(sval, g_sval);
    SYM_ADDR(wenc, g_wenc);  SYM_ADDR(wgc1, g_wgc1); SYM_ADDR(wgc2, g_wgc2);
    SYM_ADDR(wgc3, g_wgc3);  SYM_ADDR(wnode, g_wnode); SYM_ADDR(wnei, g_wnei);
    SYM_ADDR(bnp, g_bnp);    SYM_ADDR(bvp1, g_bvp1);  SYM_ADDR(bvp2, g_bvp2);

    // dynamic smem sizes (bytes)
    const int SMEM_ENC  = (128*(256+8) + 128*(256+8))*2 + 128*4;
    const int SMEM_G128 = (128*(128+8) + 128*(128+8))*2 + 128*4;
    const int SMEM_G64  = (128*(128+8) +  64*(128+8))*2 +  64*4;
    const int SMEM_POOL = (64*(128+8)*2 + 128*(128+8)*2)*2 + (640+640+64)*4;  // 109824
    cudaFuncSetAttribute((const void*)mma_gemm<128,256,true ,false,true >, cudaFuncAttributeMaxDynamicSharedMemorySize, SMEM_ENC);
    cudaFuncSetAttribute((const void*)mma_gemm<128,128,false,true ,true >, cudaFuncAttributeMaxDynamicSharedMemorySize, SMEM_G128);
    cudaFuncSetAttribute((const void*)mma_gemm<64 ,128,false,true ,true >, cudaFuncAttributeMaxDynamicSharedMemorySize, SMEM_G64);
    cudaFuncSetAttribute((const void*)mma_pool,                            cudaFuncAttributeMaxDynamicSharedMemorySize, SMEM_POOL);

    const int TPB = 256;
    const int edge_blocks = (NE + TPB - 1) / TPB;
    const int warp_blocks = (NN * 32 + TPB - 1) / TPB;
    const int MT128 = (NN + 127) / 128;   // 391
    const int MT64  = (NN + 63) / 64;     // 782

    // weight prep FIRST (zeros cnt, folds gc biases); independent of edges
    prep_all<<<(5*NH*NH + 255)/256, 256>>>(W_enc, W_gc1, W_gc2, W_gc3, W_node, W_nei,
                                           b_node, b_nei, b_gc1, b_gc2,
                                           wenc, wgc1, wgc2, wgc3, wnode, wnei,
                                           bnp, bvp1, bvp2, cnt);

    // CSR build
    count_kernel<<<edge_blocks, TPB>>>(esrc, cnt, NE);
    scan_kernel<<<1, 1024>>>(cnt, rowptr, fill, NN);
    scatter_kernel<<<edge_blocks, TPB>>>(esrc, edst, eval, fill, sdst, sval, NE);

    // encoder: fp32 in -> bf16 out
    mma_gemm<128,256,true ,false,true ><<<MT128, 256, SMEM_ENC >>>(x, wenc, b_enc, xorg, NN);
    // gc1 gemm (tb = xorg @ W_gc1)
    mma_gemm<128,128,false,true ,true ><<<MT128, 256, SMEM_G128>>>(xorg, wgc1, nullptr, tb, NN);
    // pool1 (fused spmm + bilinear; gc1 bias folded into bvp1)
    mma_pool<<<MT64, 256, SMEM_POOL>>>(xorg, tb, rowptr, sdst, sval,
                                       wnode, wnei, bnp, bvp1, x1, NN);
    // gc2 gemm
    mma_gemm<128,128,false,true ,true ><<<MT128, 256, SMEM_G128>>>(x1, wgc2, nullptr, tb, NN);
    // pool2 (fused; gc2 bias folded into bvp2)
    mma_pool<<<MT64, 256, SMEM_POOL>>>(x1, tb, rowptr, sdst, sval,
                                       wnode, wnei, bnp, bvp2, x2, NN);
    // gc3 gemm -> t3 (bf16)
    mma_gemm<64,128,false,true ,true ><<<MT128, 256, SMEM_G64>>>(x2, wgc3, nullptr, t3, NN);
    // final spmm + bias + log_softmax (fp32 accum/output)
    spmm64_lsm_kernel<<<warp_blocks, TPB>>>(t3, rowptr, sdst, sval, b_gc3, out, NN);
}

// round 13
// speedup vs baseline: 1.1422x; 1.1422x over previous
#include <cuda_runtime.h>
#include <cuda_bf16.h>
#include <math.h>
#include <stdint.h>

#define NN    50000
#define NFEAT 256
#define NH    128
#define NC    64
#define NE    800000

// ---------------- static scratch ----------------
__device__ __align__(16) __nv_bfloat16 g_xorg[(size_t)NN*NH];
__device__ __align__(16) __nv_bfloat16 g_tb  [(size_t)NN*NH];
__device__ __align__(16) __nv_bfloat16 g_h   [(size_t)NN*NH];
__device__ __align__(16) __nv_bfloat16 g_x1  [(size_t)NN*NH];
__device__ __align__(16) __nv_bfloat16 g_x2  [(size_t)NN*NH];
__device__ __align__(16) __nv_bfloat16 g_t3  [(size_t)NN*NC];
__device__ __align__(16) __nv_bfloat16 g_wenc [NH*NFEAT];   // [N=128][K=256]
__device__ __align__(16) __nv_bfloat16 g_wgc1 [NH*NH];
__device__ __align__(16) __nv_bfloat16 g_wgc2 [NH*NH];
__device__ __align__(16) __nv_bfloat16 g_wgc3 [NC*NH];      // [64][128]
__device__ __align__(16) __nv_bfloat16 g_wnode[5*NH*NH];    // permuted [640][128]
__device__ __align__(16) __nv_bfloat16 g_wnei [5*NH*NH];
__device__ float g_bnp[5*NH];
__device__ float g_bvp[5*NH];
__device__ int   g_cnt[NN+1];
__device__ int   g_rowptr[NN+1];
__device__ int   g_fill[NN];
__device__ int   g_sdst[NE];
__device__ float g_sval[NE];

// ---------------- PTX helpers (sm_80+ portable; no tcgen05) ----------------
__device__ __forceinline__ uint32_t smem_u32(const void* p){
    uint32_t a;
    asm("{ .reg .u64 t; cvta.to.shared.u64 t, %1; cvt.u32.u64 %0, t; }" : "=r"(a) : "l"(p));
    return a;
}
__device__ __forceinline__ void ldsm_x4(uint32_t* r, uint32_t addr){
    asm volatile("ldmatrix.sync.aligned.m8n8.x4.shared.b16 {%0,%1,%2,%3}, [%4];"
        : "=r"(r[0]),"=r"(r[1]),"=r"(r[2]),"=r"(r[3]) : "r"(addr));
}
__device__ __forceinline__ void ldsm_x2(uint32_t* r, uint32_t addr){
    asm volatile("ldmatrix.sync.aligned.m8n8.x2.shared.b16 {%0,%1}, [%2];"
        : "=r"(r[0]),"=r"(r[1]) : "r"(addr));
}
__device__ __forceinline__ void mma16816(float* c, const uint32_t* a, const uint32_t* b){
    asm volatile("mma.sync.aligned.m16n8k16.row.col.f32.bf16.bf16.f32 "
        "{%0,%1,%2,%3}, {%4,%5,%6,%7}, {%8,%9}, {%0,%1,%2,%3};"
        : "+f"(c[0]), "+f"(c[1]), "+f"(c[2]), "+f"(c[3])
        : "r"(a[0]), "r"(a[1]), "r"(a[2]), "r"(a[3]), "r"(b[0]), "r"(b[1]));
}
__device__ __forceinline__ float warp_sum(float v){
    #pragma unroll
    for(int o=16;o;o>>=1) v += __shfl_xor_sync(0xffffffffu, v, o);
    return v;
}
__device__ __forceinline__ float warp_max(float v){
    #pragma unroll
    for(int o=16;o;o>>=1) v = fmaxf(v, __shfl_xor_sync(0xffffffffu, v, o));
    return v;
}
__device__ __forceinline__ float bf2f(__nv_bfloat16 b){ return __bfloat162float(b); }

// ---------------- CSR build ----------------
__global__ void count_kernel(const int* __restrict__ src, int* cnt, int ne){
    int i = blockIdx.x*blockDim.x + threadIdx.x;
    if(i < ne) atomicAdd(&cnt[src[i]], 1);
}
__global__ void scan_kernel(const int* __restrict__ cnt, int* rowptr, int* fill, int n){
    __shared__ int sh[1024];
    int tid = threadIdx.x;
    int chunk = (n + 1023) >> 10;
    int s0 = tid*chunk, s1 = min(s0+chunk, n);
    int s = 0;
    for(int i=s0;i<s1;i++) s += cnt[i];
    sh[tid] = s;
    __syncthreads();
    for(int off=1; off<1024; off<<=1){
        int v = (tid >= off) ? sh[tid-off] : 0;
        __syncthreads();
        sh[tid] += v;
        __syncthreads();
    }
    int run = sh[tid] - s;
    for(int i=s0;i<s1;i++){
        rowptr[i] = run; fill[i] = run; run += cnt[i];
    }
    if(tid == 1023) rowptr[n] = sh[1023];
}
__global__ void scatter_kernel(const int* __restrict__ src, const int* __restrict__ dst,
                               const float* __restrict__ val,
                               int* fill, int* sdst, float* sval, int ne){
    int i = blockIdx.x*blockDim.x + threadIdx.x;
    if(i < ne){
        int p = atomicAdd(&fill[src[i]], 1);
        sdst[p] = dst[i];
        sval[p] = val[i];
    }
}

// ---------------- fused weight prep (+ cnt zeroing; launched FIRST) ----------------
__global__ void prep_all(const float* __restrict__ W_enc, const float* __restrict__ W_gc1,
                         const float* __restrict__ W_gc2, const float* __restrict__ W_gc3,
                         const float* __restrict__ Wn,    const float* __restrict__ Wv,
                         const float* __restrict__ bn,    const float* __restrict__ bv,
                         __nv_bfloat16* wenc, __nv_bfloat16* wgc1, __nv_bfloat16* wgc2,
                         __nv_bfloat16* wgc3, __nv_bfloat16* wn_t, __nv_bfloat16* wv_t,
                         float* bn_p, float* bv_p, int* cnt)
{
    int i = blockIdx.x*256 + threadIdx.x;
    if(i < NN + 1) cnt[i] = 0;
    if(i < NH*NFEAT){
        int n = i / NFEAT, k = i % NFEAT;
        wenc[i] = __float2bfloat16(W_enc[(size_t)k*NH + n]);
    }
    if(i < NH*NH){
        int n = i / NH, k = i % NH;
        wgc1[i] = __float2bfloat16(W_gc1[(size_t)k*NH + n]);
        wgc2[i] = __float2bfloat16(W_gc2[(size_t)k*NH + n]);
    }
    if(i < NC*NH){
        int n = i / NH, k = i % NH;
        wgc3[i] = __float2bfloat16(W_gc3[(size_t)k*NC + n]);
    }
    if(i < 640*128){
        int np = i >> 7, k = i & 127;
        int t = np >> 7, j = np & 127;
        int col = j*5 + t;
        wn_t[i] = __float2bfloat16(Wn[(size_t)k*640 + col]);
        wv_t[i] = __float2bfloat16(Wv[(size_t)k*640 + col]);
    }
    if(i < 640){
        int t = i >> 7, j = i & 127;
        int col = j*5 + t;
        bn_p[i] = bn[col];
        bv_p[i] = bv[col];
    }
}

// ---------------- bf16 warp-MMA GEMM ----------------
// C[M][BN] = A[M][K] @ Bt[BN][K]^T (+bias). A fp32 or bf16; C fp32 or bf16.
// 256 threads = 8 warps as 4(M) x 2(N). Block tile 128 x BN.
template<int BN, int K, bool BIAS, bool INBF, bool OUTBF>
__global__ __launch_bounds__(256) void mma_gemm(
    const void* __restrict__ Ain, const __nv_bfloat16* __restrict__ Bt,
    const float* __restrict__ bias, void* __restrict__ Cout, int M)
{
    constexpr int P  = K + 8;
    constexpr int NW = BN / 2;
    constexpr int NF = NW / 8;
    extern __shared__ __align__(16) char smem[];
    __nv_bfloat16* As = (__nv_bfloat16*)smem;
    __nv_bfloat16* Bs = As + 128*P;
    float* bias_s = (float*)(Bs + (size_t)BN*P);

    const int tid = threadIdx.x, lane = tid & 31, wid = tid >> 5;
    const int wm = wid & 3, wn = wid >> 2;
    const int bm = blockIdx.x * 128;

    if(INBF){
        const __nv_bfloat16* A = (const __nv_bfloat16*)Ain;
        for(int i=tid; i<128*(K/8); i+=256){
            int r = i / (K/8), k = (i % (K/8)) * 8;
            uint4 u = make_uint4(0u,0u,0u,0u);
            if(bm + r < M) u = *(const uint4*)(A + (size_t)(bm+r)*K + k);
            *(uint4*)&As[r*P + k] = u;
        }
    } else {
        const float* A = (const float*)Ain;
        for(int i=tid; i<128*(K/4); i+=256){
            int r = i / (K/4), k = (i % (K/4)) * 4;
            float4 v = make_float4(0.f,0.f,0.f,0.f);
            if(bm + r < M) v = *(const float4*)(A + (size_t)(bm+r)*K + k);
            __nv_bfloat162 lo = __floats2bfloat162_rn(v.x, v.y);
            __nv_bfloat162 hi = __floats2bfloat162_rn(v.z, v.w);
            uint2 u; u.x = *(uint32_t*)&lo; u.y = *(uint32_t*)&hi;
            *(uint2*)&As[r*P + k] = u;
        }
    }
    for(int i=tid; i<BN*(K/8); i+=256){
        int r = i / (K/8), k = (i % (K/8)) * 8;
        *(uint4*)&Bs[r*P + k] = *(const uint4*)(Bt + (size_t)r*K + k);
    }
    if(BIAS){ for(int i=tid; i<BN; i+=256) bias_s[i] = bias[i]; }
    __syncthreads();

    const uint32_t as_b = smem_u32(As);
    const uint32_t bs_b = smem_u32(Bs);

    float acc[2][NF][4];
    #pragma unroll
    for(int f=0;f<2;f++)
        #pragma unroll
        for(int g=0;g<NF;g++)
            #pragma unroll
            for(int v=0;v<4;v++) acc[f][g][v] = 0.f;

    #pragma unroll
    for(int k0=0; k0<K; k0+=16){
        uint32_t a[2][4];
        #pragma unroll
        for(int f=0;f<2;f++)
            ldsm_x4(a[f], as_b + (uint32_t)(((wm*32 + f*16 + (lane&15))*P + k0 + (lane>>4)*8) << 1));
        uint32_t b[NF][2];
        #pragma unroll
        for(int g=0;g<NF;g++)
            ldsm_x2(b[g], bs_b + (uint32_t)(((wn*NW + g*8 + (lane&7))*P + k0 + ((lane>>3)&1)*8) << 1));
        #pragma unroll
        for(int f=0;f<2;f++)
            #pragma unroll
            for(int g=0;g<NF;g++)
                mma16816(acc[f][g], a[f], b[g]);
    }

    #pragma unroll
    for(int f=0;f<2;f++){
        int r0 = bm + wm*32 + f*16 + (lane>>2);
        #pragma unroll
        for(int g=0;g<NF;g++){
            int c = wn*NW + g*8 + (lane&3)*2;
            float bx = BIAS ? bias_s[c]   : 0.f;
            float by = BIAS ? bias_s[c+1] : 0.f;
            if(OUTBF){
                __nv_bfloat16* C = (__nv_bfloat16*)Cout;
                if(r0 < M)
                    *(__nv_bfloat162*)(C + (size_t)r0*BN + c) =
                        __floats2bfloat162_rn(acc[f][g][0]+bx, acc[f][g][1]+by);
                if(r0 + 8 < M)
                    *(__nv_bfloat162*)(C + (size_t)(r0+8)*BN + c) =
                        __floats2bfloat162_rn(acc[f][g][2]+bx, acc[f][g][3]+by);
            } else {
                float* C = (float*)Cout;
                if(r0 < M)
                    *(float2*)(C + (size_t)r0*BN + c) = make_float2(acc[f][g][0]+bx, acc[f][g][1]+by);
                if(r0 + 8 < M)
                    *(float2*)(C + (size_t)(r0+8)*BN + c) = make_float2(acc[f][g][2]+bx, acc[f][g][3]+by);
            }
        }
    }
}

// ---------------- fused bilinear pool (64-row blocks, 2 CTAs/SM — proven version) ----------------
__global__ __launch_bounds__(256) void mma_pool(
    const __nv_bfloat16* __restrict__ A1, const __nv_bfloat16* __restrict__ A2,
    const __nv_bfloat16* __restrict__ Wn, const __nv_bfloat16* __restrict__ Wv,
    const float* __restrict__ bnp, const float* __restrict__ bvp,
    __nv_bfloat16* __restrict__ Out, int M)
{
    constexpr int K = 128, P = K + 8;
    extern __shared__ __align__(16) char smem[];
    __nv_bfloat16* A1s = (__nv_bfloat16*)smem;       // 64 x P
    __nv_bfloat16* A2s = A1s + 64*P;
    __nv_bfloat16* Bns = A2s + 64*P;                 // 128 x P
    __nv_bfloat16* Bvs = Bns + 128*P;
    float* bn_s   = (float*)(Bvs + 128*P);           // 640
    float* bv_s   = bn_s + 640;
    float* rowsum = bv_s + 640;                      // 64

    const int tid = threadIdx.x, lane = tid & 31, wid = tid >> 5;
    const int wm = wid & 1, wn = wid >> 1;           // 2 x 4
    const int bm = blockIdx.x * 64;

    // load A tiles (bf16 straight copy)
    for(int i=tid; i<64*16; i+=256){
        int r = i >> 4, k = (i & 15) * 8;
        uint4 u1 = make_uint4(0u,0u,0u,0u), u2 = u1;
        if(bm + r < M){
            u1 = *(const uint4*)(A1 + (size_t)(bm+r)*K + k);
            u2 = *(const uint4*)(A2 + (size_t)(bm+r)*K + k);
        }
        *(uint4*)&A1s[r*P + k] = u1;
        *(uint4*)&A2s[r*P + k] = u2;
    }
    for(int i=tid; i<640; i+=256){ bn_s[i] = bnp[i]; bv_s[i] = bvp[i]; }
    if(tid < 64) rowsum[tid] = 0.f;

    const uint32_t a1_b = smem_u32(A1s);
    const uint32_t a2_b = smem_u32(A2s);
    const uint32_t bn_b = smem_u32(Bns);
    const uint32_t bv_b = smem_u32(Bvs);

    float acc[2][4][4];
    #pragma unroll
    for(int f=0;f<2;f++)
        #pragma unroll
        for(int g=0;g<4;g++)
            #pragma unroll
            for(int v=0;v<4;v++) acc[f][g][v] = 0.f;

    for(int t=0; t<5; t++){
        __syncthreads();
        for(int i=tid; i<128*16; i+=256){
            int r = i >> 4, k = (i & 15) * 8;
            *(uint4*)&Bns[r*P + k] = *(const uint4*)(Wn + ((size_t)t*128 + r)*K + k);
            *(uint4*)&Bvs[r*P + k] = *(const uint4*)(Wv + ((size_t)t*128 + r)*K + k);
        }
        __syncthreads();

        float U[2][4][4], V[2][4][4];
        #pragma unroll
        for(int f=0;f<2;f++)
            #pragma unroll
            for(int g=0;g<4;g++)
                #pragma unroll
                for(int v=0;v<4;v++){ U[f][g][v]=0.f; V[f][g][v]=0.f; }

        #pragma unroll
        for(int k0=0; k0<K; k0+=16){
            uint32_t a1[2][4], a2[2][4];
            #pragma unroll
            for(int f=0;f<2;f++){
                uint32_t ao = (uint32_t)(((wm*32 + f*16 + (lane&15))*P + k0 + (lane>>4)*8) << 1);
                ldsm_x4(a1[f], a1_b + ao);
                ldsm_x4(a2[f], a2_b + ao);
            }
            uint32_t b1[4][2], b2[4][2];
            #pragma unroll
            for(int g=0;g<4;g++){
                uint32_t bo = (uint32_t)(((wn*32 + g*8 + (lane&7))*P + k0 + ((lane>>3)&1)*8) << 1);
                ldsm_x2(b1[g], bn_b + bo);
                ldsm_x2(b2[g], bv_b + bo);
            }
            #pragma unroll
            for(int f=0;f<2;f++)
                #pragma unroll
                for(int g=0;g<4;g++){
                    mma16816(U[f][g], a1[f], b1[g]);
                    mma16816(V[f][g], a2[f], b2[g]);
                }
        }

        #pragma unroll
        for(int f=0;f<2;f++)
            #pragma unroll
            for(int g=0;g<4;g++){
                int c = wn*32 + g*8 + (lane&3)*2;
                float bnx = bn_s[t*128 + c], bny = bn_s[t*128 + c + 1];
                float bvx = bv_s[t*128 + c], bvy = bv_s[t*128 + c + 1];
                acc[f][g][0] += (U[f][g][0]+bnx)*(V[f][g][0]+bvx);
                acc[f][g][1] += (U[f][g][1]+bny)*(V[f][g][1]+bvy);
                acc[f][g][2] += (U[f][g][2]+bnx)*(V[f][g][2]+bvx);
                acc[f][g][3] += (U[f][g][3]+bny)*(V[f][g][3]+bvy);
            }
    }

    // row |g| sums
    #pragma unroll
    for(int f=0;f<2;f++){
        float s0 = 0.f, s1 = 0.f;
        #pragma unroll
        for(int g=0;g<4;g++){
            s0 += fabsf(acc[f][g][0]) + fabsf(acc[f][g][1]);
            s1 += fabsf(acc[f][g][2]) + fabsf(acc[f][g][3]);
        }
        s0 += __shfl_xor_sync(0xffffffffu, s0, 1);
        s0 += __shfl_xor_sync(0xffffffffu, s0, 2);
        s1 += __shfl_xor_sync(0xffffffffu, s1, 1);
        s1 += __shfl_xor_sync(0xffffffffu, s1, 2);
        if((lane & 3) == 0){
            atomicAdd(&rowsum[wm*32 + f*16 + (lane>>2)], s0);
            atomicAdd(&rowsum[wm*32 + f*16 + (lane>>2) + 8], s1);
        }
    }
    __syncthreads();

    // normalize + store bf16
    #pragma unroll
    for(int f=0;f<2;f++){
        int lr = wm*32 + f*16 + (lane>>2);
        float inv0 = 1.f / fmaxf(sqrtf(rowsum[lr]),     1e-12f);
        float inv1 = 1.f / fmaxf(sqrtf(rowsum[lr + 8]), 1e-12f);
        int r0 = bm + lr;
        #pragma unroll
        for(int g=0;g<4;g++){
            int c = wn*32 + g*8 + (lane&3)*2;
            if(r0 < M){
                float ox = copysignf(sqrtf(fabsf(acc[f][g][0])), acc[f][g][0]) * inv0;
                float oy = copysignf(sqrtf(fabsf(acc[f][g][1])), acc[f][g][1]) * inv0;
                *(__nv_bfloat162*)(Out + (size_t)r0*NH + c) = __floats2bfloat162_rn(ox, oy);
            }
            if(r0 + 8 < M){
                float ox = copysignf(sqrtf(fabsf(acc[f][g][2])), acc[f][g][2]) * inv1;
                float oy = copysignf(sqrtf(fabsf(acc[f][g][3])), acc[f][g][3]) * inv1;
                *(__nv_bfloat162*)(Out + (size_t)(r0+8)*NH + c) = __floats2bfloat162_rn(ox, oy);
            }
        }
    }
}

// ---------------- spmm (CSR, warp per row, 128 bf16 cols, 4-deep unroll) ----------------
__global__ void spmm128_kernel(const __nv_bfloat16* __restrict__ h,
                               const int* __restrict__ rowptr,
                               const int* __restrict__ sdst,
                               const float* __restrict__ sval,
                               const float* __restrict__ bias,
                               __nv_bfloat16* __restrict__ out, int n)
{
    int w = (blockIdx.x*blockDim.x + threadIdx.x) >> 5;
    if(w >= n) return;
    int lane = threadIdx.x & 31;
    int b = rowptr[w], e = rowptr[w+1];

    float4 a0 = make_float4(0.f,0.f,0.f,0.f);
    float4 a1 = make_float4(0.f,0.f,0.f,0.f);
    float4 a2 = make_float4(0.f,0.f,0.f,0.f);
    float4 a3 = make_float4(0.f,0.f,0.f,0.f);
    int j = b;
    for(; j+3 < e; j+=4){
        int d0 = sdst[j], d1 = sdst[j+1], d2 = sdst[j+2], d3 = sdst[j+3];
        float v0 = sval[j], v1 = sval[j+1], v2 = sval[j+2], v3 = sval[j+3];
        uint2 u0 = *(const uint2*)(h + (size_t)d0*NH + lane*4);
        uint2 u1 = *(const uint2*)(h + (size_t)d1*NH + lane*4);
        uint2 u2 = *(const uint2*)(h + (size_t)d2*NH + lane*4);
        uint2 u3 = *(const uint2*)(h + (size_t)d3*NH + lane*4);
        __nv_bfloat162 p0 = *(__nv_bfloat162*)&u0.x, q0 = *(__nv_bfloat162*)&u0.y;
        __nv_bfloat162 p1 = *(__nv_bfloat162*)&u1.x, q1 = *(__nv_bfloat162*)&u1.y;
        __nv_bfloat162 p2 = *(__nv_bfloat162*)&u2.x, q2 = *(__nv_bfloat162*)&u2.y;
        __nv_bfloat162 p3 = *(__nv_bfloat162*)&u3.x, q3 = *(__nv_bfloat162*)&u3.y;
        a0.x += v0*bf2f(p0.x); a0.y += v0*bf2f(p0.y); a0.z += v0*bf2f(q0.x); a0.w += v0*bf2f(q0.y);
        a1.x += v1*bf2f(p1.x); a1.y += v1*bf2f(p1.y); a1.z += v1*bf2f(q1.x); a1.w += v1*bf2f(q1.y);
        a2.x += v2*bf2f(p2.x); a2.y += v2*bf2f(p2.y); a2.z += v2*bf2f(q2.x); a2.w += v2*bf2f(q2.y);
        a3.x += v3*bf2f(p3.x); a3.y += v3*bf2f(p3.y); a3.z += v3*bf2f(q3.x); a3.w += v3*bf2f(q3.y);
    }
    for(; j < e; j++){
        int d0 = sdst[j]; float v0 = sval[j];
        uint2 u0 = *(const uint2*)(h + (size_t)d0*NH + lane*4);
        __nv_bfloat162 p0 = *(__nv_bfloat162*)&u0.x, q0 = *(__nv_bfloat162*)&u0.y;
        a0.x += v0*bf2f(p0.x); a0.y += v0*bf2f(p0.y); a0.z += v0*bf2f(q0.x); a0.w += v0*bf2f(q0.y);
    }
    float4 bb = *(const float4*)(bias + lane*4);
    a0.x += a1.x + a2.x + a3.x + bb.x;
    a0.y += a1.y + a2.y + a3.y + bb.y;
    a0.z += a1.z + a2.z + a3.z + bb.z;
    a0.w += a1.w + a2.w + a3.w + bb.w;
    uint2 o;
    __nv_bfloat162 o0 = __floats2bfloat162_rn(a0.x, a0.y);
    __nv_bfloat162 o1 = __floats2bfloat162_rn(a0.z, a0.w);
    o.x = *(uint32_t*)&o0; o.y = *(uint32_t*)&o1;
    *(uint2*)(out + (size_t)w*NH + lane*4) = o;
}

// ---------------- spmm 64 bf16 cols + bias + log_softmax ----------------
__global__ void spmm64_lsm_kernel(const __nv_bfloat16* __restrict__ t3,
                                  const int* __restrict__ rowptr,
                                  const int* __restrict__ sdst,
                                  const float* __restrict__ sval,
                                  const float* __restrict__ bias,
                                  float* __restrict__ out, int n)
{
    int w = (blockIdx.x*blockDim.x + threadIdx.x) >> 5;
    if(w >= n) return;
    int lane = threadIdx.x & 31;
    int b = rowptr[w], e = rowptr[w+1];

    float2 acc = make_float2(0.f, 0.f);
    float2 acc2 = make_float2(0.f, 0.f);
    int j = b;
    for(; j+1 < e; j+=2){
        int d0 = sdst[j], d1 = sdst[j+1];
        float v0 = sval[j], v1 = sval[j+1];
        __nv_bfloat162 h0 = *(const __nv_bfloat162*)(t3 + (size_t)d0*NC + lane*2);
        __nv_bfloat162 h1 = *(const __nv_bfloat162*)(t3 + (size_t)d1*NC + lane*2);
        acc.x  += v0*bf2f(h0.x); acc.y  += v0*bf2f(h0.y);
        acc2.x += v1*bf2f(h1.x); acc2.y += v1*bf2f(h1.y);
    }
    if(j < e){
        int d = sdst[j]; float v = sval[j];
        __nv_bfloat162 hv = *(const __nv_bfloat162*)(t3 + (size_t)d*NC + lane*2);
        acc.x += v*bf2f(hv.x); acc.y += v*bf2f(hv.y);
    }
    float2 bb = *(const float2*)(bias + lane*2);
    acc.x += acc2.x + bb.x; acc.y += acc2.y + bb.y;

    float m = warp_max(fmaxf(acc.x, acc.y));
    float s = warp_sum(expf(acc.x - m) + expf(acc.y - m));
    float lse = m + logf(s);
    *(float2*)(out + (size_t)w*NC + lane*2) = make_float2(acc.x - lse, acc.y - lse);
}

// ---------------- launch ----------------
#define SYM_ADDR(p, sym) cudaGetSymbolAddress((void**)&(p), sym)

extern "C" void kernel_launch(void* const* d_in, const int* in_sizes, int n_in,
                              void* d_out, int out_size)
{
    const float* x      = (const float*)d_in[0];
    const int*   esrc   = (const int*)  d_in[1];
    const int*   edst   = (const int*)  d_in[2];
    const float* eval   = (const float*)d_in[3];
    const float* W_enc  = (const float*)d_in[4];
    const float* b_enc  = (const float*)d_in[5];
    const float* W_gc1  = (const float*)d_in[6];
    const float* b_gc1  = (const float*)d_in[7];
    const float* W_gc2  = (const float*)d_in[8];
    const float* b_gc2  = (const float*)d_in[9];
    const float* W_gc3  = (const float*)d_in[10];
    const float* b_gc3  = (const float*)d_in[11];
    const float* W_node = (const float*)d_in[12];
    const float* b_node = (const float*)d_in[13];
    const float* W_nei  = (const float*)d_in[14];
    const float* b_nei  = (const float*)d_in[15];
    float* out = (float*)d_out;

    float *sval, *bnp, *bvp;
    int *cnt, *rowptr, *fill, *sdst;
    __nv_bfloat16 *xorg, *tb, *h, *x1, *x2, *t3;
    __nv_bfloat16 *wenc, *wgc1, *wgc2, *wgc3, *wnode, *wnei;
    SYM_ADDR(xorg, g_xorg);  SYM_ADDR(tb, g_tb);    SYM_ADDR(h, g_h);
    SYM_ADDR(x1, g_x1);      SYM_ADDR(x2, g_x2);    SYM_ADDR(t3, g_t3);
    SYM_ADDR(cnt, g_cnt);    SYM_ADDR(rowptr, g_rowptr);
    SYM_ADDR(fill, g_fill);  SYM_ADDR(sdst, g_sdst); SYM_ADDR(sval, g_sval);
    SYM_ADDR(wenc, g_wenc);  SYM_ADDR(wgc1, g_wgc1); SYM_ADDR(wgc2, g_wgc2);
    SYM_ADDR(wgc3, g_wgc3);  SYM_ADDR(wnode, g_wnode); SYM_ADDR(wnei, g_wnei);
    SYM_ADDR(bnp, g_bnp);    SYM_ADDR(bvp, g_bvp);

    // dynamic smem sizes (bytes)
    const int SMEM_ENC  = (128*(256+8) + 128*(256+8))*2 + 128*4;
    const int SMEM_G128 = (128*(128+8) + 128*(128+8))*2 + 128*4;
    const int SMEM_G64  = (128*(128+8) +  64*(128+8))*2 +  64*4;
    const int SMEM_POOL = (64*(128+8)*2 + 128*(128+8)*2)*2 + (640+640+64)*4;  // 109824
    cudaFuncSetAttribute((const void*)mma_gemm<128,256,true ,false,true >, cudaFuncAttributeMaxDynamicSharedMemorySize, SMEM_ENC);
    cudaFuncSetAttribute((const void*)mma_gemm<128,128,false,true ,true >, cudaFuncAttributeMaxDynamicSharedMemorySize, SMEM_G128);
    cudaFuncSetAttribute((const void*)mma_gemm<64 ,128,false,true ,true >, cudaFuncAttributeMaxDynamicSharedMemorySize, SMEM_G64);
    cudaFuncSetAttribute((const void*)mma_pool,                            cudaFuncAttributeMaxDynamicSharedMemorySize, SMEM_POOL);

    const int TPB = 256;
    const int edge_blocks = (NE + TPB - 1) / TPB;
    const int warp_blocks = (NN * 32 + TPB - 1) / TPB;
    const int MT128 = (NN + 127) / 128;   // 391
    const int MT64  = (NN + 63) / 64;     // 782

    // weight prep FIRST (also zeros cnt); independent of edges
    prep_all<<<(5*NH*NH + 255)/256, 256>>>(W_enc, W_gc1, W_gc2, W_gc3, W_node, W_nei,
                                           b_node, b_nei,
                                           wenc, wgc1, wgc2, wgc3, wnode, wnei, bnp, bvp, cnt);

    // CSR build
    count_kernel<<<edge_blocks, TPB>>>(esrc, cnt, NE);
    scan_kernel<<<1, 1024>>>(cnt, rowptr, fill, NN);
    scatter_kernel<<<edge_blocks, TPB>>>(esrc, edst, eval, fill, sdst, sval, NE);

    // encoder: fp32 in -> bf16 out
    mma_gemm<128,256,true ,false,true ><<<MT128, 256, SMEM_ENC >>>(x, wenc, b_enc, xorg, NN);
    // gc1
    mma_gemm<128,128,false,true ,true ><<<MT128, 256, SMEM_G128>>>(xorg, wgc1, nullptr, tb, NN);
    spmm128_kernel<<<warp_blocks, TPB>>>(tb, rowptr, sdst, sval, b_gc1, h, NN);
    // pool1 (fused, 64-row blocks)
    mma_pool<<<MT64, 256, SMEM_POOL>>>(xorg, h, wnode, wnei, bnp, bvp, x1, NN);
    // gc2
    mma_gemm<128,128,false,true ,true ><<<MT128, 256, SMEM_G128>>>(x1, wgc2, nullptr, tb, NN);
    spmm128_kernel<<<warp_blocks, TPB>>>(tb, rowptr, sdst, sval, b_gc2, h, NN);
    // pool2 (fused)
    mma_pool<<<MT64, 256, SMEM_POOL>>>(x1, h, wnode, wnei, bnp, bvp, x2, NN);
    // gc3 -> t3 (bf16)
    mma_gemm<64,128,false,true ,true ><<<MT128, 256, SMEM_G64>>>(x2, wgc3, nullptr, t3, NN);
    // final spmm + bias + log_softmax (fp32 accum/output)
    spmm64_lsm_kernel<<<warp_blocks, TPB>>>(t3, rowptr, sdst, sval, b_gc3, out, NN);
}

// round 14
// speedup vs baseline: 1.3147x; 1.1510x over previous
#include <cuda_runtime.h>
#include <cuda_bf16.h>
#include <math.h>
#include <stdint.h>

#define NN    50000
#define NFEAT 256
#define NH    128
#define NC    64
#define NE    800000

// ---------------- static scratch ----------------
__device__ __align__(16) __nv_bfloat16 g_xorg[(size_t)NN*NH];
__device__ __align__(16) __nv_bfloat16 g_tb  [(size_t)NN*NH];
__device__ __align__(16) __nv_bfloat16 g_h   [(size_t)NN*NH];
__device__ __align__(16) __nv_bfloat16 g_x1  [(size_t)NN*NH];
__device__ __align__(16) __nv_bfloat16 g_x2  [(size_t)NN*NH];
__device__ __align__(16) __nv_bfloat16 g_t3  [(size_t)NN*NC];
__device__ __align__(16) __nv_bfloat16 g_wenc [NH*NFEAT];   // [N=128][K=256]
__device__ __align__(16) __nv_bfloat16 g_wgc1 [NH*NH];
__device__ __align__(16) __nv_bfloat16 g_wgc2 [NH*NH];
__device__ __align__(16) __nv_bfloat16 g_wgc3 [NC*NH];      // [64][128]
__device__ __align__(16) __nv_bfloat16 g_wnode[5*NH*NH];    // permuted [640][128]
__device__ __align__(16) __nv_bfloat16 g_wnei [5*NH*NH];
__device__ float g_bnp[5*NH];
__device__ float g_bvp[5*NH];
__device__ int   g_cnt[NN+1];
__device__ int   g_rowptr[NN+1];
__device__ int   g_fill[NN];
__device__ int   g_sdst[NE];
__device__ float g_sval[NE];

// ---------------- PTX helpers (sm_80+ portable; no tcgen05) ----------------
__device__ __forceinline__ uint32_t smem_u32(const void* p){
    uint32_t a;
    asm("{ .reg .u64 t; cvta.to.shared.u64 t, %1; cvt.u32.u64 %0, t; }" : "=r"(a) : "l"(p));
    return a;
}
__device__ __forceinline__ void ldsm_x4(uint32_t* r, uint32_t addr){
    asm volatile("ldmatrix.sync.aligned.m8n8.x4.shared.b16 {%0,%1,%2,%3}, [%4];"
        : "=r"(r[0]),"=r"(r[1]),"=r"(r[2]),"=r"(r[3]) : "r"(addr));
}
__device__ __forceinline__ void ldsm_x2(uint32_t* r, uint32_t addr){
    asm volatile("ldmatrix.sync.aligned.m8n8.x2.shared.b16 {%0,%1}, [%2];"
        : "=r"(r[0]),"=r"(r[1]) : "r"(addr));
}
__device__ __forceinline__ void mma16816(float* c, const uint32_t* a, const uint32_t* b){
    asm volatile("mma.sync.aligned.m16n8k16.row.col.f32.bf16.bf16.f32 "
        "{%0,%1,%2,%3}, {%4,%5,%6,%7}, {%8,%9}, {%0,%1,%2,%3};"
        : "+f"(c[0]), "+f"(c[1]), "+f"(c[2]), "+f"(c[3])
        : "r"(a[0]), "r"(a[1]), "r"(a[2]), "r"(a[3]), "r"(b[0]), "r"(b[1]));
}
__device__ __forceinline__ float warp_sum(float v){
    #pragma unroll
    for(int o=16;o;o>>=1) v += __shfl_xor_sync(0xffffffffu, v, o);
    return v;
}
__device__ __forceinline__ float warp_max(float v){
    #pragma unroll
    for(int o=16;o;o>>=1) v = fmaxf(v, __shfl_xor_sync(0xffffffffu, v, o));
    return v;
}
__device__ __forceinline__ float bf2f(__nv_bfloat16 b){ return __bfloat162float(b); }

// ---------------- CSR build ----------------
__global__ void zero_cnt_kernel(int* cnt){
    for(int i = blockIdx.x*blockDim.x + threadIdx.x; i < NN + 1; i += gridDim.x*blockDim.x)
        cnt[i] = 0;
}
__global__ void count_kernel(const int* __restrict__ src, int* cnt, int ne){
    int i = blockIdx.x*blockDim.x + threadIdx.x;
    if(i < ne) atomicAdd(&cnt[src[i]], 1);
}
__global__ void scan_kernel(const int* __restrict__ cnt, int* rowptr, int* fill, int n){
    __shared__ int sh[1024];
    int tid = threadIdx.x;
    int chunk = (n + 1023) >> 10;
    int s0 = tid*chunk, s1 = min(s0+chunk, n);
    int s = 0;
    for(int i=s0;i<s1;i++) s += cnt[i];
    sh[tid] = s;
    __syncthreads();
    for(int off=1; off<1024; off<<=1){
        int v = (tid >= off) ? sh[tid-off] : 0;
        __syncthreads();
        sh[tid] += v;
        __syncthreads();
    }
    int run = sh[tid] - s;
    for(int i=s0;i<s1;i++){
        rowptr[i] = run; fill[i] = run; run += cnt[i];
    }
    if(tid == 1023) rowptr[n] = sh[1023];
}
__global__ void scatter_kernel(const int* __restrict__ src, const int* __restrict__ dst,
                               const float* __restrict__ val,
                               int* fill, int* sdst, float* sval, int ne){
    int i = blockIdx.x*blockDim.x + threadIdx.x;
    if(i < ne){
        int p = atomicAdd(&fill[src[i]], 1);
        sdst[p] = dst[i];
        sval[p] = val[i];
    }
}

// ---------------- fused weight prep ----------------
__global__ void prep_all(const float* __restrict__ W_enc, const float* __restrict__ W_gc1,
                         const float* __restrict__ W_gc2, const float* __restrict__ W_gc3,
                         const float* __restrict__ Wn,    const float* __restrict__ Wv,
                         const float* __restrict__ bn,    const float* __restrict__ bv,
                         __nv_bfloat16* wenc, __nv_bfloat16* wgc1, __nv_bfloat16* wgc2,
                         __nv_bfloat16* wgc3, __nv_bfloat16* wn_t, __nv_bfloat16* wv_t,
                         float* bn_p, float* bv_p)
{
    int i = blockIdx.x*256 + threadIdx.x;
    if(i < NH*NFEAT){
        int n = i / NFEAT, k = i % NFEAT;
        wenc[i] = __float2bfloat16(W_enc[(size_t)k*NH + n]);
    }
    if(i < NH*NH){
        int n = i / NH, k = i % NH;
        wgc1[i] = __float2bfloat16(W_gc1[(size_t)k*NH + n]);
        wgc2[i] = __float2bfloat16(W_gc2[(size_t)k*NH + n]);
    }
    if(i < NC*NH){
        int n = i / NH, k = i % NH;
        wgc3[i] = __float2bfloat16(W_gc3[(size_t)k*NC + n]);
    }
    if(i < 640*128){
        int np = i >> 7, k = i & 127;
        int t = np >> 7, j = np & 127;
        int col = j*5 + t;
        wn_t[i] = __float2bfloat16(Wn[(size_t)k*640 + col]);
        wv_t[i] = __float2bfloat16(Wv[(size_t)k*640 + col]);
    }
    if(i < 640){
        int t = i >> 7, j = i & 127;
        int col = j*5 + t;
        bn_p[i] = bn[col];
        bv_p[i] = bv[col];
    }
}

// ---------------- bf16 warp-MMA GEMM ----------------
// C[M][BN] = A[M][K] @ Bt[BN][K]^T (+bias). A fp32 or bf16; C fp32 or bf16.
// 256 threads = 8 warps as 4(M) x 2(N). Block tile 128 x BN.
template<int BN, int K, bool BIAS, bool INBF, bool OUTBF>
__global__ __launch_bounds__(256) void mma_gemm(
    const void* __restrict__ Ain, const __nv_bfloat16* __restrict__ Bt,
    const float* __restrict__ bias, void* __restrict__ Cout, int M)
{
    constexpr int P  = K + 8;
    constexpr int NW = BN / 2;
    constexpr int NF = NW / 8;
    extern __shared__ __align__(16) char smem[];
    __nv_bfloat16* As = (__nv_bfloat16*)smem;
    __nv_bfloat16* Bs = As + 128*P;
    float* bias_s = (float*)(Bs + (size_t)BN*P);

    const int tid = threadIdx.x, lane = tid & 31, wid = tid >> 5;
    const int wm = wid & 3, wn = wid >> 2;
    const int bm = blockIdx.x * 128;

    if(INBF){
        const __nv_bfloat16* A = (const __nv_bfloat16*)Ain;
        for(int i=tid; i<128*(K/8); i+=256){
            int r = i / (K/8), k = (i % (K/8)) * 8;
            uint4 u = make_uint4(0u,0u,0u,0u);
            if(bm + r < M) u = *(const uint4*)(A + (size_t)(bm+r)*K + k);
            *(uint4*)&As[r*P + k] = u;
        }
    } else {
        const float* A = (const float*)Ain;
        for(int i=tid; i<128*(K/4); i+=256){
            int r = i / (K/4), k = (i % (K/4)) * 4;
            float4 v = make_float4(0.f,0.f,0.f,0.f);
            if(bm + r < M) v = *(const float4*)(A + (size_t)(bm+r)*K + k);
            __nv_bfloat162 lo = __floats2bfloat162_rn(v.x, v.y);
            __nv_bfloat162 hi = __floats2bfloat162_rn(v.z, v.w);
            uint2 u; u.x = *(uint32_t*)&lo; u.y = *(uint32_t*)&hi;
            *(uint2*)&As[r*P + k] = u;
        }
    }
    for(int i=tid; i<BN*(K/8); i+=256){
        int r = i / (K/8), k = (i % (K/8)) * 8;
        *(uint4*)&Bs[r*P + k] = *(const uint4*)(Bt + (size_t)r*K + k);
    }
    if(BIAS){ for(int i=tid; i<BN; i+=256) bias_s[i] = bias[i]; }
    __syncthreads();

    const uint32_t as_b = smem_u32(As);
    const uint32_t bs_b = smem_u32(Bs);

    float acc[2][NF][4];
    #pragma unroll
    for(int f=0;f<2;f++)
        #pragma unroll
        for(int g=0;g<NF;g++)
            #pragma unroll
            for(int v=0;v<4;v++) acc[f][g][v] = 0.f;

    #pragma unroll
    for(int k0=0; k0<K; k0+=16){
        uint32_t a[2][4];
        #pragma unroll
        for(int f=0;f<2;f++)
            ldsm_x4(a[f], as_b + (uint32_t)(((wm*32 + f*16 + (lane&15))*P + k0 + (lane>>4)*8) << 1));
        uint32_t b[NF][2];
        #pragma unroll
        for(int g=0;g<NF;g++)
            ldsm_x2(b[g], bs_b + (uint32_t)(((wn*NW + g*8 + (lane&7))*P + k0 + ((lane>>3)&1)*8) << 1));
        #pragma unroll
        for(int f=0;f<2;f++)
            #pragma unroll
            for(int g=0;g<NF;g++)
                mma16816(acc[f][g], a[f], b[g]);
    }

    #pragma unroll
    for(int f=0;f<2;f++){
        int r0 = bm + wm*32 + f*16 + (lane>>2);
        #pragma unroll
        for(int g=0;g<NF;g++){
            int c = wn*NW + g*8 + (lane&3)*2;
            float bx = BIAS ? bias_s[c]   : 0.f;
            float by = BIAS ? bias_s[c+1] : 0.f;
            if(OUTBF){
                __nv_bfloat16* C = (__nv_bfloat16*)Cout;
                if(r0 < M)
                    *(__nv_bfloat162*)(C + (size_t)r0*BN + c) =
                        __floats2bfloat162_rn(acc[f][g][0]+bx, acc[f][g][1]+by);
                if(r0 + 8 < M)
                    *(__nv_bfloat162*)(C + (size_t)(r0+8)*BN + c) =
                        __floats2bfloat162_rn(acc[f][g][2]+bx, acc[f][g][3]+by);
            } else {
                float* C = (float*)Cout;
                if(r0 < M)
                    *(float2*)(C + (size_t)r0*BN + c) = make_float2(acc[f][g][0]+bx, acc[f][g][1]+by);
                if(r0 + 8 < M)
                    *(float2*)(C + (size_t)(r0+8)*BN + c) = make_float2(acc[f][g][2]+bx, acc[f][g][3]+by);
            }
        }
    }
}

// ---------------- fused bilinear pool (64-row blocks, 2 CTAs/SM — proven version) ----------------
__global__ __launch_bounds__(256) void mma_pool(
    const __nv_bfloat16* __restrict__ A1, const __nv_bfloat16* __restrict__ A2,
    const __nv_bfloat16* __restrict__ Wn, const __nv_bfloat16* __restrict__ Wv,
    const float* __restrict__ bnp, const float* __restrict__ bvp,
    __nv_bfloat16* __restrict__ Out, int M)
{
    constexpr int K = 128, P = K + 8;
    extern __shared__ __align__(16) char smem[];
    __nv_bfloat16* A1s = (__nv_bfloat16*)smem;       // 64 x P
    __nv_bfloat16* A2s = A1s + 64*P;
    __nv_bfloat16* Bns = A2s + 64*P;                 // 128 x P
    __nv_bfloat16* Bvs = Bns + 128*P;
    float* bn_s   = (float*)(Bvs + 128*P);           // 640
    float* bv_s   = bn_s + 640;
    float* rowsum = bv_s + 640;                      // 64

    const int tid = threadIdx.x, lane = tid & 31, wid = tid >> 5;
    const int wm = wid & 1, wn = wid >> 1;           // 2 x 4
    const int bm = blockIdx.x * 64;

    for(int i=tid; i<64*16; i+=256){
        int r = i >> 4, k = (i & 15) * 8;
        uint4 u1 = make_uint4(0u,0u,0u,0u), u2 = u1;
        if(bm + r < M){
            u1 = *(const uint4*)(A1 + (size_t)(bm+r)*K + k);
            u2 = *(const uint4*)(A2 + (size_t)(bm+r)*K + k);
        }
        *(uint4*)&A1s[r*P + k] = u1;
        *(uint4*)&A2s[r*P + k] = u2;
    }
    for(int i=tid; i<640; i+=256){ bn_s[i] = bnp[i]; bv_s[i] = bvp[i]; }
    if(tid < 64) rowsum[tid] = 0.f;

    const uint32_t a1_b = smem_u32(A1s);
    const uint32_t a2_b = smem_u32(A2s);
    const uint32_t bn_b = smem_u32(Bns);
    const uint32_t bv_b = smem_u32(Bvs);

    float acc[2][4][4];
    #pragma unroll
    for(int f=0;f<2;f++)
        #pragma unroll
        for(int g=0;g<4;g++)
            #pragma unroll
            for(int v=0;v<4;v++) acc[f][g][v] = 0.f;

    for(int t=0; t<5; t++){
        __syncthreads();
        for(int i=tid; i<128*16; i+=256){
            int r = i >> 4, k = (i & 15) * 8;
            *(uint4*)&Bns[r*P + k] = *(const uint4*)(Wn + ((size_t)t*128 + r)*K + k);
            *(uint4*)&Bvs[r*P + k] = *(const uint4*)(Wv + ((size_t)t*128 + r)*K + k);
        }
        __syncthreads();

        float U[2][4][4], V[2][4][4];
        #pragma unroll
        for(int f=0;f<2;f++)
            #pragma unroll
            for(int g=0;g<4;g++)
                #pragma unroll
                for(int v=0;v<4;v++){ U[f][g][v]=0.f; V[f][g][v]=0.f; }

        #pragma unroll
        for(int k0=0; k0<K; k0+=16){
            uint32_t a1[2][4], a2[2][4];
            #pragma unroll
            for(int f=0;f<2;f++){
                uint32_t ao = (uint32_t)(((wm*32 + f*16 + (lane&15))*P + k0 + (lane>>4)*8) << 1);
                ldsm_x4(a1[f], a1_b + ao);
                ldsm_x4(a2[f], a2_b + ao);
            }
            uint32_t b1[4][2], b2[4][2];
            #pragma unroll
            for(int g=0;g<4;g++){
                uint32_t bo = (uint32_t)(((wn*32 + g*8 + (lane&7))*P + k0 + ((lane>>3)&1)*8) << 1);
                ldsm_x2(b1[g], bn_b + bo);
                ldsm_x2(b2[g], bv_b + bo);
            }
            #pragma unroll
            for(int f=0;f<2;f++)
                #pragma unroll
                for(int g=0;g<4;g++){
                    mma16816(U[f][g], a1[f], b1[g]);
                    mma16816(V[f][g], a2[f], b2[g]);
                }
        }

        #pragma unroll
        for(int f=0;f<2;f++)
            #pragma unroll
            for(int g=0;g<4;g++){
                int c = wn*32 + g*8 + (lane&3)*2;
                float bnx = bn_s[t*128 + c], bny = bn_s[t*128 + c + 1];
                float bvx = bv_s[t*128 + c], bvy = bv_s[t*128 + c + 1];
                acc[f][g][0] += (U[f][g][0]+bnx)*(V[f][g][0]+bvx);
                acc[f][g][1] += (U[f][g][1]+bny)*(V[f][g][1]+bvy);
                acc[f][g][2] += (U[f][g][2]+bnx)*(V[f][g][2]+bvx);
                acc[f][g][3] += (U[f][g][3]+bny)*(V[f][g][3]+bvy);
            }
    }

    #pragma unroll
    for(int f=0;f<2;f++){
        float s0 = 0.f, s1 = 0.f;
        #pragma unroll
        for(int g=0;g<4;g++){
            s0 += fabsf(acc[f][g][0]) + fabsf(acc[f][g][1]);
            s1 += fabsf(acc[f][g][2]) + fabsf(acc[f][g][3]);
        }
        s0 += __shfl_xor_sync(0xffffffffu, s0, 1);
        s0 += __shfl_xor_sync(0xffffffffu, s0, 2);
        s1 += __shfl_xor_sync(0xffffffffu, s1, 1);
        s1 += __shfl_xor_sync(0xffffffffu, s1, 2);
        if((lane & 3) == 0){
            atomicAdd(&rowsum[wm*32 + f*16 + (lane>>2)], s0);
            atomicAdd(&rowsum[wm*32 + f*16 + (lane>>2) + 8], s1);
        }
    }
    __syncthreads();

    #pragma unroll
    for(int f=0;f<2;f++){
        int lr = wm*32 + f*16 + (lane>>2);
        float inv0 = 1.f / fmaxf(sqrtf(rowsum[lr]),     1e-12f);
        float inv1 = 1.f / fmaxf(sqrtf(rowsum[lr + 8]), 1e-12f);
        int r0 = bm + lr;
        #pragma unroll
        for(int g=0;g<4;g++){
            int c = wn*32 + g*8 + (lane&3)*2;
            if(r0 < M){
                float ox = copysignf(sqrtf(fabsf(acc[f][g][0])), acc[f][g][0]) * inv0;
                float oy = copysignf(sqrtf(fabsf(acc[f][g][1])), acc[f][g][1]) * inv0;
                *(__nv_bfloat162*)(Out + (size_t)r0*NH + c) = __floats2bfloat162_rn(ox, oy);
            }
            if(r0 + 8 < M){
                float ox = copysignf(sqrtf(fabsf(acc[f][g][2])), acc[f][g][2]) * inv1;
                float oy = copysignf(sqrtf(fabsf(acc[f][g][3])), acc[f][g][3]) * inv1;
                *(__nv_bfloat162*)(Out + (size_t)(r0+8)*NH + c) = __floats2bfloat162_rn(ox, oy);
            }
        }
    }
}

// ---------------- spmm (CSR, warp per row, 128 bf16 cols, 4-deep unroll) ----------------
__global__ void spmm128_kernel(const __nv_bfloat16* __restrict__ h,
                               const int* __restrict__ rowptr,
                               const int* __restrict__ sdst,
                               const float* __restrict__ sval,
                               const float* __restrict__ bias,
                               __nv_bfloat16* __restrict__ out, int n)
{
    int w = (blockIdx.x*blockDim.x + threadIdx.x) >> 5;
    if(w >= n) return;
    int lane = threadIdx.x & 31;
    int b = rowptr[w], e = rowptr[w+1];

    float4 a0 = make_float4(0.f,0.f,0.f,0.f);
    float4 a1 = make_float4(0.f,0.f,0.f,0.f);
    float4 a2 = make_float4(0.f,0.f,0.f,0.f);
    float4 a3 = make_float4(0.f,0.f,0.f,0.f);
    int j = b;
    for(; j+3 < e; j+=4){
        int d0 = sdst[j], d1 = sdst[j+1], d2 = sdst[j+2], d3 = sdst[j+3];
        float v0 = sval[j], v1 = sval[j+1], v2 = sval[j+2], v3 = sval[j+3];
        uint2 u0 = *(const uint2*)(h + (size_t)d0*NH + lane*4);
        uint2 u1 = *(const uint2*)(h + (size_t)d1*NH + lane*4);
        uint2 u2 = *(const uint2*)(h + (size_t)d2*NH + lane*4);
        uint2 u3 = *(const uint2*)(h + (size_t)d3*NH + lane*4);
        __nv_bfloat162 p0 = *(__nv_bfloat162*)&u0.x, q0 = *(__nv_bfloat162*)&u0.y;
        __nv_bfloat162 p1 = *(__nv_bfloat162*)&u1.x, q1 = *(__nv_bfloat162*)&u1.y;
        __nv_bfloat162 p2 = *(__nv_bfloat162*)&u2.x, q2 = *(__nv_bfloat162*)&u2.y;
        __nv_bfloat162 p3 = *(__nv_bfloat162*)&u3.x, q3 = *(__nv_bfloat162*)&u3.y;
        a0.x += v0*bf2f(p0.x); a0.y += v0*bf2f(p0.y); a0.z += v0*bf2f(q0.x); a0.w += v0*bf2f(q0.y);
        a1.x += v1*bf2f(p1.x); a1.y += v1*bf2f(p1.y); a1.z += v1*bf2f(q1.x); a1.w += v1*bf2f(q1.y);
        a2.x += v2*bf2f(p2.x); a2.y += v2*bf2f(p2.y); a2.z += v2*bf2f(q2.x); a2.w += v2*bf2f(q2.y);
        a3.x += v3*bf2f(p3.x); a3.y += v3*bf2f(p3.y); a3.z += v3*bf2f(q3.x); a3.w += v3*bf2f(q3.y);
    }
    for(; j < e; j++){
        int d0 = sdst[j]; float v0 = sval[j];
        uint2 u0 = *(const uint2*)(h + (size_t)d0*NH + lane*4);
        __nv_bfloat162 p0 = *(__nv_bfloat162*)&u0.x, q0 = *(__nv_bfloat162*)&u0.y;
        a0.x += v0*bf2f(p0.x); a0.y += v0*bf2f(p0.y); a0.z += v0*bf2f(q0.x); a0.w += v0*bf2f(q0.y);
    }
    float4 bb = *(const float4*)(bias + lane*4);
    a0.x += a1.x + a2.x + a3.x + bb.x;
    a0.y += a1.y + a2.y + a3.y + bb.y;
    a0.z += a1.z + a2.z + a3.z + bb.z;
    a0.w += a1.w + a2.w + a3.w + bb.w;
    uint2 o;
    __nv_bfloat162 o0 = __floats2bfloat162_rn(a0.x, a0.y);
    __nv_bfloat162 o1 = __floats2bfloat162_rn(a0.z, a0.w);
    o.x = *(uint32_t*)&o0; o.y = *(uint32_t*)&o1;
    *(uint2*)(out + (size_t)w*NH + lane*4) = o;
}

// ---------------- spmm 64 bf16 cols + bias + log_softmax ----------------
__global__ void spmm64_lsm_kernel(const __nv_bfloat16* __restrict__ t3,
                                  const int* __restrict__ rowptr,
                                  const int* __restrict__ sdst,
                                  const float* __restrict__ sval,
                                  const float* __restrict__ bias,
                                  float* __restrict__ out, int n)
{
    int w = (blockIdx.x*blockDim.x + threadIdx.x) >> 5;
    if(w >= n) return;
    int lane = threadIdx.x & 31;
    int b = rowptr[w], e = rowptr[w+1];

    float2 acc = make_float2(0.f, 0.f);
    float2 acc2 = make_float2(0.f, 0.f);
    int j = b;
    for(; j+1 < e; j+=2){
        int d0 = sdst[j], d1 = sdst[j+1];
        float v0 = sval[j], v1 = sval[j+1];
        __nv_bfloat162 h0 = *(const __nv_bfloat162*)(t3 + (size_t)d0*NC + lane*2);
        __nv_bfloat162 h1 = *(const __nv_bfloat162*)(t3 + (size_t)d1*NC + lane*2);
        acc.x  += v0*bf2f(h0.x); acc.y  += v0*bf2f(h0.y);
        acc2.x += v1*bf2f(h1.x); acc2.y += v1*bf2f(h1.y);
    }
    if(j < e){
        int d = sdst[j]; float v = sval[j];
        __nv_bfloat162 hv = *(const __nv_bfloat162*)(t3 + (size_t)d*NC + lane*2);
        acc.x += v*bf2f(hv.x); acc.y += v*bf2f(hv.y);
    }
    float2 bb = *(const float2*)(bias + lane*2);
    acc.x += acc2.x + bb.x; acc.y += acc2.y + bb.y;

    float m = warp_max(fmaxf(acc.x, acc.y));
    float s = warp_sum(expf(acc.x - m) + expf(acc.y - m));
    float lse = m + logf(s);
    *(float2*)(out + (size_t)w*NC + lane*2) = make_float2(acc.x - lse, acc.y - lse);
}

// ---------------- launch ----------------
#define SYM_ADDR(p, sym) cudaGetSymbolAddress((void**)&(p), sym)

extern "C" void kernel_launch(void* const* d_in, const int* in_sizes, int n_in,
                              void* d_out, int out_size)
{
    const float* x      = (const float*)d_in[0];
    const int*   esrc   = (const int*)  d_in[1];
    const int*   edst   = (const int*)  d_in[2];
    const float* eval   = (const float*)d_in[3];
    const float* W_enc  = (const float*)d_in[4];
    const float* b_enc  = (const float*)d_in[5];
    const float* W_gc1  = (const float*)d_in[6];
    const float* b_gc1  = (const float*)d_in[7];
    const float* W_gc2  = (const float*)d_in[8];
    const float* b_gc2  = (const float*)d_in[9];
    const float* W_gc3  = (const float*)d_in[10];
    const float* b_gc3  = (const float*)d_in[11];
    const float* W_node = (const float*)d_in[12];
    const float* b_node = (const float*)d_in[13];
    const float* W_nei  = (const float*)d_in[14];
    const float* b_nei  = (const float*)d_in[15];
    float* out = (float*)d_out;

    float *sval, *bnp, *bvp;
    int *cnt, *rowptr, *fill, *sdst;
    __nv_bfloat16 *xorg, *tb, *h, *x1, *x2, *t3;
    __nv_bfloat16 *wenc, *wgc1, *wgc2, *wgc3, *wnode, *wnei;
    SYM_ADDR(xorg, g_xorg);  SYM_ADDR(tb, g_tb);    SYM_ADDR(h, g_h);
    SYM_ADDR(x1, g_x1);      SYM_ADDR(x2, g_x2);    SYM_ADDR(t3, g_t3);
    SYM_ADDR(cnt, g_cnt);    SYM_ADDR(rowptr, g_rowptr);
    SYM_ADDR(fill, g_fill);  SYM_ADDR(sdst, g_sdst); SYM_ADDR(sval, g_sval);
    SYM_ADDR(wenc, g_wenc);  SYM_ADDR(wgc1, g_wgc1); SYM_ADDR(wgc2, g_wgc2);
    SYM_ADDR(wgc3, g_wgc3);  SYM_ADDR(wnode, g_wnode); SYM_ADDR(wnei, g_wnei);
    SYM_ADDR(bnp, g_bnp);    SYM_ADDR(bvp, g_bvp);

    // dynamic smem sizes (bytes)
    const int SMEM_ENC  = (128*(256+8) + 128*(256+8))*2 + 128*4;
    const int SMEM_G128 = (128*(128+8) + 128*(128+8))*2 + 128*4;
    const int SMEM_G64  = (128*(128+8) +  64*(128+8))*2 +  64*4;
    const int SMEM_POOL = (64*(128+8)*2 + 128*(128+8)*2)*2 + (640+640+64)*4;  // 109824
    cudaFuncSetAttribute((const void*)mma_gemm<128,256,true ,false,true >, cudaFuncAttributeMaxDynamicSharedMemorySize, SMEM_ENC);
    cudaFuncSetAttribute((const void*)mma_gemm<128,128,false,true ,true >, cudaFuncAttributeMaxDynamicSharedMemorySize, SMEM_G128);
    cudaFuncSetAttribute((const void*)mma_gemm<64 ,128,false,true ,true >, cudaFuncAttributeMaxDynamicSharedMemorySize, SMEM_G64);
    cudaFuncSetAttribute((const void*)mma_pool,                            cudaFuncAttributeMaxDynamicSharedMemorySize, SMEM_POOL);

    // one-time stream/event creation (host resources only; no device memory)
    static cudaStream_t s_side = nullptr;
    static cudaEvent_t  s_fork = nullptr, s_join = nullptr;
    if(s_side == nullptr){
        cudaStreamCreateWithFlags(&s_side, cudaStreamNonBlocking);
        cudaEventCreateWithFlags(&s_fork, cudaEventDisableTiming);
        cudaEventCreateWithFlags(&s_join, cudaEventDisableTiming);
    }

    const int TPB = 256;
    const int edge_blocks = (NE + TPB - 1) / TPB;
    const int warp_blocks = (NN * 32 + TPB - 1) / TPB;
    const int MT128 = (NN + 127) / 128;   // 391
    const int MT64  = (NN + 63) / 64;     // 782

    // ---- fork: CSR chain on side stream, prep/encoder/gc1 on main stream ----
    cudaEventRecord(s_fork, 0);
    cudaStreamWaitEvent(s_side, s_fork, 0);

    // side stream: CSR build
    zero_cnt_kernel<<<64, TPB, 0, s_side>>>(cnt);
    count_kernel<<<edge_blocks, TPB, 0, s_side>>>(esrc, cnt, NE);
    scan_kernel<<<1, 1024, 0, s_side>>>(cnt, rowptr, fill, NN);
    scatter_kernel<<<edge_blocks, TPB, 0, s_side>>>(esrc, edst, eval, fill, sdst, sval, NE);
    cudaEventRecord(s_join, s_side);

    // main stream: weight prep + encoder + gc1 gemm (independent of CSR)
    prep_all<<<(5*NH*NH + 255)/256, 256>>>(W_enc, W_gc1, W_gc2, W_gc3, W_node, W_nei,
                                           b_node, b_nei,
                                           wenc, wgc1, wgc2, wgc3, wnode, wnei, bnp, bvp);
    mma_gemm<128,256,true ,false,true ><<<MT128, 256, SMEM_ENC >>>(x, wenc, b_enc, xorg, NN);
    mma_gemm<128,128,false,true ,true ><<<MT128, 256, SMEM_G128>>>(xorg, wgc1, nullptr, tb, NN);

    // ---- join: everything below needs both chains ----
    cudaStreamWaitEvent(0, s_join, 0);

    spmm128_kernel<<<warp_blocks, TPB>>>(tb, rowptr, sdst, sval, b_gc1, h, NN);
    // pool1
    mma_pool<<<MT64, 256, SMEM_POOL>>>(xorg, h, wnode, wnei, bnp, bvp, x1, NN);
    // gc2
    mma_gemm<128,128,false,true ,true ><<<MT128, 256, SMEM_G128>>>(x1, wgc2, nullptr, tb, NN);
    spmm128_kernel<<<warp_blocks, TPB>>>(tb, rowptr, sdst, sval, b_gc2, h, NN);
    // pool2
    mma_pool<<<MT64, 256, SMEM_POOL>>>(x1, h, wnode, wnei, bnp, bvp, x2, NN);
    // gc3 -> t3 (bf16)
    mma_gemm<64,128,false,true ,true ><<<MT128, 256, SMEM_G64>>>(x2, wgc3, nullptr, t3, NN);
    // final spmm + bias + log_softmax
    spmm64_lsm_kernel<<<warp_blocks, TPB>>>(t3, rowptr, sdst, sval, b_gc3, out, NN);
}

// round 15
// speedup vs baseline: 1.3616x; 1.0357x over previous
#include <cuda_runtime.h>
#include <cuda_bf16.h>
#include <math.h>
#include <stdint.h>

#define NN    50000
#define NFEAT 256
#define NH    128
#define NC    64
#define NE    800000
#define HALF0 25024            // rows in half 0 (multiple of 128)
#define HALF1 (NN - HALF0)     // 24976

// ---------------- static scratch ----------------
__device__ __align__(16) __nv_bfloat16 g_xorg[(size_t)NN*NH];
__device__ __align__(16) __nv_bfloat16 g_tb  [(size_t)NN*NH];
__device__ __align__(16) __nv_bfloat16 g_tb2 [(size_t)NN*NH];
__device__ __align__(16) __nv_bfloat16 g_h   [(size_t)NN*NH];
__device__ __align__(16) __nv_bfloat16 g_x1  [(size_t)NN*NH];
__device__ __align__(16) __nv_bfloat16 g_x2  [(size_t)NN*NH];
__device__ __align__(16) __nv_bfloat16 g_t3  [(size_t)NN*NC];
__device__ __align__(16) __nv_bfloat16 g_wenc [NH*NFEAT];   // [N=128][K=256]
__device__ __align__(16) __nv_bfloat16 g_wgc1 [NH*NH];
__device__ __align__(16) __nv_bfloat16 g_wgc2 [NH*NH];
__device__ __align__(16) __nv_bfloat16 g_wgc3 [NC*NH];      // [64][128]
__device__ __align__(16) __nv_bfloat16 g_wnode[5*NH*NH];    // permuted [640][128]
__device__ __align__(16) __nv_bfloat16 g_wnei [5*NH*NH];
__device__ float g_bnp[5*NH];
__device__ float g_bvp[5*NH];
__device__ int   g_cnt[NN+1];
__device__ int   g_rowptr[NN+1];
__device__ int   g_fill[NN];
__device__ int   g_sdst[NE];
__device__ float g_sval[NE];

// ---------------- PTX helpers (sm_80+ portable; no tcgen05) ----------------
__device__ __forceinline__ uint32_t smem_u32(const void* p){
    uint32_t a;
    asm("{ .reg .u64 t; cvta.to.shared.u64 t, %1; cvt.u32.u64 %0, t; }" : "=r"(a) : "l"(p));
    return a;
}
__device__ __forceinline__ void ldsm_x4(uint32_t* r, uint32_t addr){
    asm volatile("ldmatrix.sync.aligned.m8n8.x4.shared.b16 {%0,%1,%2,%3}, [%4];"
        : "=r"(r[0]),"=r"(r[1]),"=r"(r[2]),"=r"(r[3]) : "r"(addr));
}
__device__ __forceinline__ void ldsm_x2(uint32_t* r, uint32_t addr){
    asm volatile("ldmatrix.sync.aligned.m8n8.x2.shared.b16 {%0,%1}, [%2];"
        : "=r"(r[0]),"=r"(r[1]) : "r"(addr));
}
__device__ __forceinline__ void mma16816(float* c, const uint32_t* a, const uint32_t* b){
    asm volatile("mma.sync.aligned.m16n8k16.row.col.f32.bf16.bf16.f32 "
        "{%0,%1,%2,%3}, {%4,%5,%6,%7}, {%8,%9}, {%0,%1,%2,%3};"
        : "+f"(c[0]), "+f"(c[1]), "+f"(c[2]), "+f"(c[3])
        : "r"(a[0]), "r"(a[1]), "r"(a[2]), "r"(a[3]), "r"(b[0]), "r"(b[1]));
}
__device__ __forceinline__ float warp_sum(float v){
    #pragma unroll
    for(int o=16;o;o>>=1) v += __shfl_xor_sync(0xffffffffu, v, o);
    return v;
}
__device__ __forceinline__ float warp_max(float v){
    #pragma unroll
    for(int o=16;o;o>>=1) v = fmaxf(v, __shfl_xor_sync(0xffffffffu, v, o));
    return v;
}
__device__ __forceinline__ float bf2f(__nv_bfloat16 b){ return __bfloat162float(b); }

// ---------------- CSR build ----------------
__global__ void zero_cnt_kernel(int* cnt){
    for(int i = blockIdx.x*blockDim.x + threadIdx.x; i < NN + 1; i += gridDim.x*blockDim.x)
        cnt[i] = 0;
}
__global__ void count_kernel(const int* __restrict__ src, int* cnt, int ne){
    int i = blockIdx.x*blockDim.x + threadIdx.x;
    if(i < ne) atomicAdd(&cnt[src[i]], 1);
}
__global__ void scan_kernel(const int* __restrict__ cnt, int* rowptr, int* fill, int n){
    __shared__ int sh[1024];
    int tid = threadIdx.x;
    int chunk = (n + 1023) >> 10;
    int s0 = tid*chunk, s1 = min(s0+chunk, n);
    int s = 0;
    for(int i=s0;i<s1;i++) s += cnt[i];
    sh[tid] = s;
    __syncthreads();
    for(int off=1; off<1024; off<<=1){
        int v = (tid >= off) ? sh[tid-off] : 0;
        __syncthreads();
        sh[tid] += v;
        __syncthreads();
    }
    int run = sh[tid] - s;
    for(int i=s0;i<s1;i++){
        rowptr[i] = run; fill[i] = run; run += cnt[i];
    }
    if(tid == 1023) rowptr[n] = sh[1023];
}
__global__ void scatter_kernel(const int* __restrict__ src, const int* __restrict__ dst,
                               const float* __restrict__ val,
                               int* fill, int* sdst, float* sval, int ne){
    int i = blockIdx.x*blockDim.x + threadIdx.x;
    if(i < ne){
        int p = atomicAdd(&fill[src[i]], 1);
        sdst[p] = dst[i];
        sval[p] = val[i];
    }
}

// ---------------- fused weight prep ----------------
__global__ void prep_all(const float* __restrict__ W_enc, const float* __restrict__ W_gc1,
                         const float* __restrict__ W_gc2, const float* __restrict__ W_gc3,
                         const float* __restrict__ Wn,    const float* __restrict__ Wv,
                         const float* __restrict__ bn,    const float* __restrict__ bv,
                         __nv_bfloat16* wenc, __nv_bfloat16* wgc1, __nv_bfloat16* wgc2,
                         __nv_bfloat16* wgc3, __nv_bfloat16* wn_t, __nv_bfloat16* wv_t,
                         float* bn_p, float* bv_p)
{
    int i = blockIdx.x*256 + threadIdx.x;
    if(i < NH*NFEAT){
        int n = i / NFEAT, k = i % NFEAT;
        wenc[i] = __float2bfloat16(W_enc[(size_t)k*NH + n]);
    }
    if(i < NH*NH){
        int n = i / NH, k = i % NH;
        wgc1[i] = __float2bfloat16(W_gc1[(size_t)k*NH + n]);
        wgc2[i] = __float2bfloat16(W_gc2[(size_t)k*NH + n]);
    }
    if(i < NC*NH){
        int n = i / NH, k = i % NH;
        wgc3[i] = __float2bfloat16(W_gc3[(size_t)k*NC + n]);
    }
    if(i < 640*128){
        int np = i >> 7, k = i & 127;
        int t = np >> 7, j = np & 127;
        int col = j*5 + t;
        wn_t[i] = __float2bfloat16(Wn[(size_t)k*640 + col]);
        wv_t[i] = __float2bfloat16(Wv[(size_t)k*640 + col]);
    }
    if(i < 640){
        int t = i >> 7, j = i & 127;
        int col = j*5 + t;
        bn_p[i] = bn[col];
        bv_p[i] = bv[col];
    }
}

// ---------------- bf16 warp-MMA GEMM ----------------
template<int BN, int K, bool BIAS, bool INBF, bool OUTBF>
__global__ __launch_bounds__(256) void mma_gemm(
    const void* __restrict__ Ain, const __nv_bfloat16* __restrict__ Bt,
    const float* __restrict__ bias, void* __restrict__ Cout, int M)
{
    constexpr int P  = K + 8;
    constexpr int NW = BN / 2;
    constexpr int NF = NW / 8;
    extern __shared__ __align__(16) char smem[];
    __nv_bfloat16* As = (__nv_bfloat16*)smem;
    __nv_bfloat16* Bs = As + 128*P;
    float* bias_s = (float*)(Bs + (size_t)BN*P);

    const int tid = threadIdx.x, lane = tid & 31, wid = tid >> 5;
    const int wm = wid & 3, wn = wid >> 2;
    const int bm = blockIdx.x * 128;

    if(INBF){
        const __nv_bfloat16* A = (const __nv_bfloat16*)Ain;
        for(int i=tid; i<128*(K/8); i+=256){
            int r = i / (K/8), k = (i % (K/8)) * 8;
            uint4 u = make_uint4(0u,0u,0u,0u);
            if(bm + r < M) u = *(const uint4*)(A + (size_t)(bm+r)*K + k);
            *(uint4*)&As[r*P + k] = u;
        }
    } else {
        const float* A = (const float*)Ain;
        for(int i=tid; i<128*(K/4); i+=256){
            int r = i / (K/4), k = (i % (K/4)) * 4;
            float4 v = make_float4(0.f,0.f,0.f,0.f);
            if(bm + r < M) v = *(const float4*)(A + (size_t)(bm+r)*K + k);
            __nv_bfloat162 lo = __floats2bfloat162_rn(v.x, v.y);
            __nv_bfloat162 hi = __floats2bfloat162_rn(v.z, v.w);
            uint2 u; u.x = *(uint32_t*)&lo; u.y = *(uint32_t*)&hi;
            *(uint2*)&As[r*P + k] = u;
        }
    }
    for(int i=tid; i<BN*(K/8); i+=256){
        int r = i / (K/8), k = (i % (K/8)) * 8;
        *(uint4*)&Bs[r*P + k] = *(const uint4*)(Bt + (size_t)r*K + k);
    }
    if(BIAS){ for(int i=tid; i<BN; i+=256) bias_s[i] = bias[i]; }
    __syncthreads();

    const uint32_t as_b = smem_u32(As);
    const uint32_t bs_b = smem_u32(Bs);

    float acc[2][NF][4];
    #pragma unroll
    for(int f=0;f<2;f++)
        #pragma unroll
        for(int g=0;g<NF;g++)
            #pragma unroll
            for(int v=0;v<4;v++) acc[f][g][v] = 0.f;

    #pragma unroll
    for(int k0=0; k0<K; k0+=16){
        uint32_t a[2][4];
        #pragma unroll
        for(int f=0;f<2;f++)
            ldsm_x4(a[f], as_b + (uint32_t)(((wm*32 + f*16 + (lane&15))*P + k0 + (lane>>4)*8) << 1));
        uint32_t b[NF][2];
        #pragma unroll
        for(int g=0;g<NF;g++)
            ldsm_x2(b[g], bs_b + (uint32_t)(((wn*NW + g*8 + (lane&7))*P + k0 + ((lane>>3)&1)*8) << 1));
        #pragma unroll
        for(int f=0;f<2;f++)
            #pragma unroll
            for(int g=0;g<NF;g++)
                mma16816(acc[f][g], a[f], b[g]);
    }

    #pragma unroll
    for(int f=0;f<2;f++){
        int r0 = bm + wm*32 + f*16 + (lane>>2);
        #pragma unroll
        for(int g=0;g<NF;g++){
            int c = wn*NW + g*8 + (lane&3)*2;
            float bx = BIAS ? bias_s[c]   : 0.f;
            float by = BIAS ? bias_s[c+1] : 0.f;
            if(OUTBF){
                __nv_bfloat16* C = (__nv_bfloat16*)Cout;
                if(r0 < M)
                    *(__nv_bfloat162*)(C + (size_t)r0*BN + c) =
                        __floats2bfloat162_rn(acc[f][g][0]+bx, acc[f][g][1]+by);
                if(r0 + 8 < M)
                    *(__nv_bfloat162*)(C + (size_t)(r0+8)*BN + c) =
                        __floats2bfloat162_rn(acc[f][g][2]+bx, acc[f][g][3]+by);
            } else {
                float* C = (float*)Cout;
                if(r0 < M)
                    *(float2*)(C + (size_t)r0*BN + c) = make_float2(acc[f][g][0]+bx, acc[f][g][1]+by);
                if(r0 + 8 < M)
                    *(float2*)(C + (size_t)(r0+8)*BN + c) = make_float2(acc[f][g][2]+bx, acc[f][g][3]+by);
            }
        }
    }
}

// ---------------- fused bilinear pool (64-row blocks, 2 CTAs/SM) ----------------
__global__ __launch_bounds__(256) void mma_pool(
    const __nv_bfloat16* __restrict__ A1, const __nv_bfloat16* __restrict__ A2,
    const __nv_bfloat16* __restrict__ Wn, const __nv_bfloat16* __restrict__ Wv,
    const float* __restrict__ bnp, const float* __restrict__ bvp,
    __nv_bfloat16* __restrict__ Out, int M)
{
    constexpr int K = 128, P = K + 8;
    extern __shared__ __align__(16) char smem[];
    __nv_bfloat16* A1s = (__nv_bfloat16*)smem;       // 64 x P
    __nv_bfloat16* A2s = A1s + 64*P;
    __nv_bfloat16* Bns = A2s + 64*P;                 // 128 x P
    __nv_bfloat16* Bvs = Bns + 128*P;
    float* bn_s   = (float*)(Bvs + 128*P);           // 640
    float* bv_s   = bn_s + 640;
    float* rowsum = bv_s + 640;                      // 64

    const int tid = threadIdx.x, lane = tid & 31, wid = tid >> 5;
    const int wm = wid & 1, wn = wid >> 1;           // 2 x 4
    const int bm = blockIdx.x * 64;

    for(int i=tid; i<64*16; i+=256){
        int r = i >> 4, k = (i & 15) * 8;
        uint4 u1 = make_uint4(0u,0u,0u,0u), u2 = u1;
        if(bm + r < M){
            u1 = *(const uint4*)(A1 + (size_t)(bm+r)*K + k);
            u2 = *(const uint4*)(A2 + (size_t)(bm+r)*K + k);
        }
        *(uint4*)&A1s[r*P + k] = u1;
        *(uint4*)&A2s[r*P + k] = u2;
    }
    for(int i=tid; i<640; i+=256){ bn_s[i] = bnp[i]; bv_s[i] = bvp[i]; }
    if(tid < 64) rowsum[tid] = 0.f;

    const uint32_t a1_b = smem_u32(A1s);
    const uint32_t a2_b = smem_u32(A2s);
    const uint32_t bn_b = smem_u32(Bns);
    const uint32_t bv_b = smem_u32(Bvs);

    float acc[2][4][4];
    #pragma unroll
    for(int f=0;f<2;f++)
        #pragma unroll
        for(int g=0;g<4;g++)
            #pragma unroll
            for(int v=0;v<4;v++) acc[f][g][v] = 0.f;

    for(int t=0; t<5; t++){
        __syncthreads();
        for(int i=tid; i<128*16; i+=256){
            int r = i >> 4, k = (i & 15) * 8;
            *(uint4*)&Bns[r*P + k] = *(const uint4*)(Wn + ((size_t)t*128 + r)*K + k);
            *(uint4*)&Bvs[r*P + k] = *(const uint4*)(Wv + ((size_t)t*128 + r)*K + k);
        }
        __syncthreads();

        float U[2][4][4], V[2][4][4];
        #pragma unroll
        for(int f=0;f<2;f++)
            #pragma unroll
            for(int g=0;g<4;g++)
                #pragma unroll
                for(int v=0;v<4;v++){ U[f][g][v]=0.f; V[f][g][v]=0.f; }

        #pragma unroll
        for(int k0=0; k0<K; k0+=16){
            uint32_t a1[2][4], a2[2][4];
            #pragma unroll
            for(int f=0;f<2;f++){
                uint32_t ao = (uint32_t)(((wm*32 + f*16 + (lane&15))*P + k0 + (lane>>4)*8) << 1);
                ldsm_x4(a1[f], a1_b + ao);
                ldsm_x4(a2[f], a2_b + ao);
            }
            uint32_t b1[4][2], b2[4][2];
            #pragma unroll
            for(int g=0;g<4;g++){
                uint32_t bo = (uint32_t)(((wn*32 + g*8 + (lane&7))*P + k0 + ((lane>>3)&1)*8) << 1);
                ldsm_x2(b1[g], bn_b + bo);
                ldsm_x2(b2[g], bv_b + bo);
            }
            #pragma unroll
            for(int f=0;f<2;f++)
                #pragma unroll
                for(int g=0;g<4;g++){
                    mma16816(U[f][g], a1[f], b1[g]);
                    mma16816(V[f][g], a2[f], b2[g]);
                }
        }

        #pragma unroll
        for(int f=0;f<2;f++)
            #pragma unroll
            for(int g=0;g<4;g++){
                int c = wn*32 + g*8 + (lane&3)*2;
                float bnx = bn_s[t*128 + c], bny = bn_s[t*128 + c + 1];
                float bvx = bv_s[t*128 + c], bvy = bv_s[t*128 + c + 1];
                acc[f][g][0] += (U[f][g][0]+bnx)*(V[f][g][0]+bvx);
                acc[f][g][1] += (U[f][g][1]+bny)*(V[f][g][1]+bvy);
                acc[f][g][2] += (U[f][g][2]+bnx)*(V[f][g][2]+bvx);
                acc[f][g][3] += (U[f][g][3]+bny)*(V[f][g][3]+bvy);
            }
    }

    #pragma unroll
    for(int f=0;f<2;f++){
        float s0 = 0.f, s1 = 0.f;
        #pragma unroll
        for(int g=0;g<4;g++){
            s0 += fabsf(acc[f][g][0]) + fabsf(acc[f][g][1]);
            s1 += fabsf(acc[f][g][2]) + fabsf(acc[f][g][3]);
        }
        s0 += __shfl_xor_sync(0xffffffffu, s0, 1);
        s0 += __shfl_xor_sync(0xffffffffu, s0, 2);
        s1 += __shfl_xor_sync(0xffffffffu, s1, 1);
        s1 += __shfl_xor_sync(0xffffffffu, s1, 2);
        if((lane & 3) == 0){
            atomicAdd(&rowsum[wm*32 + f*16 + (lane>>2)], s0);
            atomicAdd(&rowsum[wm*32 + f*16 + (lane>>2) + 8], s1);
        }
    }
    __syncthreads();

    #pragma unroll
    for(int f=0;f<2;f++){
        int lr = wm*32 + f*16 + (lane>>2);
        float inv0 = 1.f / fmaxf(sqrtf(rowsum[lr]),     1e-12f);
        float inv1 = 1.f / fmaxf(sqrtf(rowsum[lr + 8]), 1e-12f);
        int r0 = bm + lr;
        #pragma unroll
        for(int g=0;g<4;g++){
            int c = wn*32 + g*8 + (lane&3)*2;
            if(r0 < M){
                float ox = copysignf(sqrtf(fabsf(acc[f][g][0])), acc[f][g][0]) * inv0;
                float oy = copysignf(sqrtf(fabsf(acc[f][g][1])), acc[f][g][1]) * inv0;
                *(__nv_bfloat162*)(Out + (size_t)r0*NH + c) = __floats2bfloat162_rn(ox, oy);
            }
            if(r0 + 8 < M){
                float ox = copysignf(sqrtf(fabsf(acc[f][g][2])), acc[f][g][2]) * inv1;
                float oy = copysignf(sqrtf(fabsf(acc[f][g][3])), acc[f][g][3]) * inv1;
                *(__nv_bfloat162*)(Out + (size_t)(r0+8)*NH + c) = __floats2bfloat162_rn(ox, oy);
            }
        }
    }
}

// ---------------- spmm (CSR, warp per row, 128 bf16 cols, 4-deep unroll) ----------------
// rowptr/out pre-offset by caller; h is the FULL gather source.
__global__ void spmm128_kernel(const __nv_bfloat16* __restrict__ h,
                               const int* __restrict__ rowptr,
                               const int* __restrict__ sdst,
                               const float* __restrict__ sval,
                               const float* __restrict__ bias,
                               __nv_bfloat16* __restrict__ out, int n)
{
    int w = (blockIdx.x*blockDim.x + threadIdx.x) >> 5;
    if(w >= n) return;
    int lane = threadIdx.x & 31;
    int b = rowptr[w], e = rowptr[w+1];

    float4 a0 = make_float4(0.f,0.f,0.f,0.f);
    float4 a1 = make_float4(0.f,0.f,0.f,0.f);
    float4 a2 = make_float4(0.f,0.f,0.f,0.f);
    float4 a3 = make_float4(0.f,0.f,0.f,0.f);
    int j = b;
    for(; j+3 < e; j+=4){
        int d0 = sdst[j], d1 = sdst[j+1], d2 = sdst[j+2], d3 = sdst[j+3];
        float v0 = sval[j], v1 = sval[j+1], v2 = sval[j+2], v3 = sval[j+3];
        uint2 u0 = *(const uint2*)(h + (size_t)d0*NH + lane*4);
        uint2 u1 = *(const uint2*)(h + (size_t)d1*NH + lane*4);
        uint2 u2 = *(const uint2*)(h + (size_t)d2*NH + lane*4);
        uint2 u3 = *(const uint2*)(h + (size_t)d3*NH + lane*4);
        __nv_bfloat162 p0 = *(__nv_bfloat162*)&u0.x, q0 = *(__nv_bfloat162*)&u0.y;
        __nv_bfloat162 p1 = *(__nv_bfloat162*)&u1.x, q1 = *(__nv_bfloat162*)&u1.y;
        __nv_bfloat162 p2 = *(__nv_bfloat162*)&u2.x, q2 = *(__nv_bfloat162*)&u2.y;
        __nv_bfloat162 p3 = *(__nv_bfloat162*)&u3.x, q3 = *(__nv_bfloat162*)&u3.y;
        a0.x += v0*bf2f(p0.x); a0.y += v0*bf2f(p0.y); a0.z += v0*bf2f(q0.x); a0.w += v0*bf2f(q0.y);
        a1.x += v1*bf2f(p1.x); a1.y += v1*bf2f(p1.y); a1.z += v1*bf2f(q1.x); a1.w += v1*bf2f(q1.y);
        a2.x += v2*bf2f(p2.x); a2.y += v2*bf2f(p2.y); a2.z += v2*bf2f(q2.x); a2.w += v2*bf2f(q2.y);
        a3.x += v3*bf2f(p3.x); a3.y += v3*bf2f(p3.y); a3.z += v3*bf2f(q3.x); a3.w += v3*bf2f(q3.y);
    }
    for(; j < e; j++){
        int d0 = sdst[j]; float v0 = sval[j];
        uint2 u0 = *(const uint2*)(h + (size_t)d0*NH + lane*4);
        __nv_bfloat162 p0 = *(__nv_bfloat162*)&u0.x, q0 = *(__nv_bfloat162*)&u0.y;
        a0.x += v0*bf2f(p0.x); a0.y += v0*bf2f(p0.y); a0.z += v0*bf2f(q0.x); a0.w += v0*bf2f(q0.y);
    }
    float4 bb = *(const float4*)(bias + lane*4);
    a0.x += a1.x + a2.x + a3.x + bb.x;
    a0.y += a1.y + a2.y + a3.y + bb.y;
    a0.z += a1.z + a2.z + a3.z + bb.z;
    a0.w += a1.w + a2.w + a3.w + bb.w;
    uint2 o;
    __nv_bfloat162 o0 = __floats2bfloat162_rn(a0.x, a0.y);
    __nv_bfloat162 o1 = __floats2bfloat162_rn(a0.z, a0.w);
    o.x = *(uint32_t*)&o0; o.y = *(uint32_t*)&o1;
    *(uint2*)(out + (size_t)w*NH + lane*4) = o;
}

// ---------------- spmm 64 bf16 cols + bias + log_softmax ----------------
__global__ void spmm64_lsm_kernel(const __nv_bfloat16* __restrict__ t3,
                                  const int* __restrict__ rowptr,
                                  const int* __restrict__ sdst,
                                  const float* __restrict__ sval,
                                  const float* __restrict__ bias,
                                  float* __restrict__ out, int n)
{
    int w = (blockIdx.x*blockDim.x + threadIdx.x) >> 5;
    if(w >= n) return;
    int lane = threadIdx.x & 31;
    int b = rowptr[w], e = rowptr[w+1];

    float2 acc = make_float2(0.f, 0.f);
    float2 acc2 = make_float2(0.f, 0.f);
    int j = b;
    for(; j+1 < e; j+=2){
        int d0 = sdst[j], d1 = sdst[j+1];
        float v0 = sval[j], v1 = sval[j+1];
        __nv_bfloat162 h0 = *(const __nv_bfloat162*)(t3 + (size_t)d0*NC + lane*2);
        __nv_bfloat162 h1 = *(const __nv_bfloat162*)(t3 + (size_t)d1*NC + lane*2);
        acc.x  += v0*bf2f(h0.x); acc.y  += v0*bf2f(h0.y);
        acc2.x += v1*bf2f(h1.x); acc2.y += v1*bf2f(h1.y);
    }
    if(j < e){
        int d = sdst[j]; float v = sval[j];
        __nv_bfloat162 hv = *(const __nv_bfloat162*)(t3 + (size_t)d*NC + lane*2);
        acc.x += v*bf2f(hv.x); acc.y += v*bf2f(hv.y);
    }
    float2 bb = *(const float2*)(bias + lane*2);
    acc.x += acc2.x + bb.x; acc.y += acc2.y + bb.y;

    float m = warp_max(fmaxf(acc.x, acc.y));
    float s = warp_sum(expf(acc.x - m) + expf(acc.y - m));
    float lse = m + logf(s);
    *(float2*)(out + (size_t)w*NC + lane*2) = make_float2(acc.x - lse, acc.y - lse);
}

// ---------------- launch ----------------
#define SYM_ADDR(p, sym) cudaGetSymbolAddress((void**)&(p), sym)

extern "C" void kernel_launch(void* const* d_in, const int* in_sizes, int n_in,
                              void* d_out, int out_size)
{
    const float* x      = (const float*)d_in[0];
    const int*   esrc   = (const int*)  d_in[1];
    const int*   edst   = (const int*)  d_in[2];
    const float* eval   = (const float*)d_in[3];
    const float* W_enc  = (const float*)d_in[4];
    const float* b_enc  = (const float*)d_in[5];
    const float* W_gc1  = (const float*)d_in[6];
    const float* b_gc1  = (const float*)d_in[7];
    const float* W_gc2  = (const float*)d_in[8];
    const float* b_gc2  = (const float*)d_in[9];
    const float* W_gc3  = (const float*)d_in[10];
    const float* b_gc3  = (const float*)d_in[11];
    const float* W_node = (const float*)d_in[12];
    const float* b_node = (const float*)d_in[13];
    const float* W_nei  = (const float*)d_in[14];
    const float* b_nei  = (const float*)d_in[15];
    float* out = (float*)d_out;

    float *sval, *bnp, *bvp;
    int *cnt, *rowptr, *fill, *sdst;
    __nv_bfloat16 *xorg, *tb, *tb2, *h, *x1, *x2, *t3;
    __nv_bfloat16 *wenc, *wgc1, *wgc2, *wgc3, *wnode, *wnei;
    SYM_ADDR(xorg, g_xorg);  SYM_ADDR(tb, g_tb);    SYM_ADDR(tb2, g_tb2);
    SYM_ADDR(h, g_h);
    SYM_ADDR(x1, g_x1);      SYM_ADDR(x2, g_x2);    SYM_ADDR(t3, g_t3);
    SYM_ADDR(cnt, g_cnt);    SYM_ADDR(rowptr, g_rowptr);
    SYM_ADDR(fill, g_fill);  SYM_ADDR(sdst, g_sdst); SYM_ADDR(sval, g_sval);
    SYM_ADDR(wenc, g_wenc);  SYM_ADDR(wgc1, g_wgc1); SYM_ADDR(wgc2, g_wgc2);
    SYM_ADDR(wgc3, g_wgc3);  SYM_ADDR(wnode, g_wnode); SYM_ADDR(wnei, g_wnei);
    SYM_ADDR(bnp, g_bnp);    SYM_ADDR(bvp, g_bvp);

    const int SMEM_ENC  = (128*(256+8) + 128*(256+8))*2 + 128*4;
    const int SMEM_G128 = (128*(128+8) + 128*(128+8))*2 + 128*4;
    const int SMEM_G64  = (128*(128+8) +  64*(128+8))*2 +  64*4;
    const int SMEM_POOL = (64*(128+8)*2 + 128*(128+8)*2)*2 + (640+640+64)*4;  // 109824
    cudaFuncSetAttribute((const void*)mma_gemm<128,256,true ,false,true >, cudaFuncAttributeMaxDynamicSharedMemorySize, SMEM_ENC);
    cudaFuncSetAttribute((const void*)mma_gemm<128,128,false,true ,true >, cudaFuncAttributeMaxDynamicSharedMemorySize, SMEM_G128);
    cudaFuncSetAttribute((const void*)mma_gemm<64 ,128,false,true ,true >, cudaFuncAttributeMaxDynamicSharedMemorySize, SMEM_G64);
    cudaFuncSetAttribute((const void*)mma_pool,                            cudaFuncAttributeMaxDynamicSharedMemorySize, SMEM_POOL);

    // one-time stream/event creation (host resources only; no device memory)
    static cudaStream_t s_side = nullptr;
    static cudaEvent_t  evFork=nullptr, evCsr=nullptr, evGc1=nullptr,
                        e0=nullptr, e1=nullptr, f1=nullptr;
    if(s_side == nullptr){
        cudaStreamCreateWithFlags(&s_side, cudaStreamNonBlocking);
        cudaEventCreateWithFlags(&evFork, cudaEventDisableTiming);
        cudaEventCreateWithFlags(&evCsr,  cudaEventDisableTiming);
        cudaEventCreateWithFlags(&evGc1,  cudaEventDisableTiming);
        cudaEventCreateWithFlags(&e0,     cudaEventDisableTiming);
        cudaEventCreateWithFlags(&e1,     cudaEventDisableTiming);
        cudaEventCreateWithFlags(&f1,     cudaEventDisableTiming);
    }

    const int TPB = 256;
    const int edge_blocks = (NE + TPB - 1) / TPB;
    const int MTG0 = (HALF0 + 127) / 128;              // 196
    const int MTG1 = (HALF1 + 127) / 128;              // 196
    const int MTP0 = (HALF0 + 63) / 64;                // 391
    const int MTP1 = (HALF1 + 63) / 64;                // 391
    const int WB0  = (HALF0 * 32 + TPB - 1) / TPB;     // 3128
    const int WB1  = (HALF1 * 32 + TPB - 1) / TPB;     // 3122
    const int WBF  = (NN * 32 + TPB - 1) / TPB;        // 6250
    const int MT128 = (NN + 127) / 128;                // 391 (full-M gemms in prefix)

    // ---- prefix fork: CSR on side ∥ prep+encoder+gc1 on main ----
    cudaEventRecord(evFork, 0);
    cudaStreamWaitEvent(s_side, evFork, 0);

    zero_cnt_kernel<<<64, TPB, 0, s_side>>>(cnt);
    count_kernel<<<edge_blocks, TPB, 0, s_side>>>(esrc, cnt, NE);
    scan_kernel<<<1, 1024, 0, s_side>>>(cnt, rowptr, fill, NN);
    scatter_kernel<<<edge_blocks, TPB, 0, s_side>>>(esrc, edst, eval, fill, sdst, sval, NE);
    cudaEventRecord(evCsr, s_side);

    prep_all<<<(5*NH*NH + 255)/256, 256>>>(W_enc, W_gc1, W_gc2, W_gc3, W_node, W_nei,
                                           b_node, b_nei,
                                           wenc, wgc1, wgc2, wgc3, wnode, wnei, bnp, bvp);
    mma_gemm<128,256,true ,false,true ><<<MT128, 256, SMEM_ENC >>>(x, wenc, b_enc, xorg, NN);
    mma_gemm<128,128,false,true ,true ><<<MT128, 256, SMEM_G128>>>(xorg, wgc1, nullptr, tb, NN);
    cudaEventRecord(evGc1, 0);

    // ---- pipelined ladder: half0 on main, half1 on side ----
    // main needs CSR; side needs gc1 (tb) — cross waits
    cudaStreamWaitEvent(0, evCsr, 0);
    cudaStreamWaitEvent(s_side, evGc1, 0);

    // layer 1
    spmm128_kernel<<<WB0, TPB>>>(tb, rowptr,           sdst, sval, b_gc1, h,                     HALF0);
    spmm128_kernel<<<WB1, TPB, 0, s_side>>>(tb, rowptr + HALF0, sdst, sval, b_gc1, h + (size_t)HALF0*NH, HALF1);
    mma_pool<<<MTP0, 256, SMEM_POOL>>>(xorg, h, wnode, wnei, bnp, bvp, x1, HALF0);
    mma_pool<<<MTP1, 256, SMEM_POOL, s_side>>>(xorg + (size_t)HALF0*NH, h + (size_t)HALF0*NH,
                                               wnode, wnei, bnp, bvp, x1 + (size_t)HALF0*NH, HALF1);
    // gc2 halves write tb2 (separate buffer — no WAR with tb gathers)
    mma_gemm<128,128,false,true ,true ><<<MTG0, 256, SMEM_G128>>>(x1, wgc2, nullptr, tb2, HALF0);
    cudaEventRecord(e0, 0);
    mma_gemm<128,128,false,true ,true ><<<MTG1, 256, SMEM_G128, s_side>>>(x1 + (size_t)HALF0*NH, wgc2, nullptr,
                                                                          tb2 + (size_t)HALF0*NH, HALF1);
    cudaEventRecord(e1, s_side);

    // layer 2 (spmm2 gathers ALL of tb2 -> cross waits)
    cudaStreamWaitEvent(0, e1, 0);
    cudaStreamWaitEvent(s_side, e0, 0);
    spmm128_kernel<<<WB0, TPB>>>(tb2, rowptr,           sdst, sval, b_gc2, h,                     HALF0);
    spmm128_kernel<<<WB1, TPB, 0, s_side>>>(tb2, rowptr + HALF0, sdst, sval, b_gc2, h + (size_t)HALF0*NH, HALF1);
    mma_pool<<<MTP0, 256, SMEM_POOL>>>(x1, h, wnode, wnei, bnp, bvp, x2, HALF0);
    mma_pool<<<MTP1, 256, SMEM_POOL, s_side>>>(x1 + (size_t)HALF0*NH, h + (size_t)HALF0*NH,
                                               wnode, wnei, bnp, bvp, x2 + (size_t)HALF0*NH, HALF1);
    mma_gemm<64,128,false,true ,true ><<<MTG0, 256, SMEM_G64>>>(x2, wgc3, nullptr, t3, HALF0);
    mma_gemm<64,128,false,true ,true ><<<MTG1, 256, SMEM_G64, s_side>>>(x2 + (size_t)HALF0*NH, wgc3, nullptr,
                                                                        t3 + (size_t)HALF0*NC, HALF1);
    cudaEventRecord(f1, s_side);

    // tail: lsm needs all of t3
    cudaStreamWaitEvent(0, f1, 0);
    spmm64_lsm_kernel<<<WBF, TPB>>>(t3, rowptr, sdst, sval, b_gc3, out, NN);
}